// round 5
// baseline (speedup 1.0000x reference)
#include <cuda_runtime.h>
#include <cuda_fp16.h>
#include <math.h>
#include <stdint.h>

#define BB 8
#define NN 192
#define HID 256
#define NF 32
#define RF 8
#define RS 16
#define IM 1024
#define LAYERS 3
#define HEADS 8
#define KS 32
#define KRS 16
#define VS 32
#define TOT 112
#define ROWS (BB*NN)          /* 1536 */
#define NPAIR (BB*NN*NN)      /* 294912 */

#define SCALE 0.14433756729740643f /* 1/sqrt(48) */
#define LN_EPS 1e-12f

// ---------------- scratch (device globals; no allocation allowed) ----------
__device__ float g_H[ROWS*HID];
__device__ float g_R[(size_t)NPAIR*RS];       // [b,i,j,s]
__device__ float g_H2[ROWS*HEADS*TOT];        // [b,n, h*112+t]
__device__ float g_A[ROWS*HEADS*KRS];         // [b,i, h*16+s]
__device__ float g_attn[ROWS*HID];
__device__ float g_tmp[ROWS*HID];

// fp16 copies (A-side activations + transposed weights)
__device__ __half g_nfh[ROWS*NF];
__device__ __half g_feat1h[ROWS*HID];
__device__ __half g_Hh[ROWS*HID];
__device__ __half g_ctxh[ROWS*HID];
__device__ __half g_attnh[ROWS*HID];
__device__ __half g_interh[ROWS*IM];
__device__ __half g_fw1t[HID*NF];
__device__ __half g_fw2t[HID*HID];
__device__ __half g_Wt[LAYERS*HEADS*TOT*HID];   // [l][896][256]
__device__ __half g_Wot[LAYERS*HID*HID];        // [l][256][256]
__device__ __half g_Wit[LAYERS*IM*HID];         // [l][1024][256]
__device__ __half g_Wo2t[LAYERS*HID*IM];        // [l][256][1024]

// ---------------- weight convert + transpose kernel -------------------------
#define NJOBS 15
struct CvtJobs {
    const float* src[NJOBS];
    __half*      dst[NJOBS];
    int K[NJOBS], N[NJOBS], tiles[NJOBS], plain[NJOBS];
};

__global__ void cvt_kernel(CvtJobs j) {
    int job = blockIdx.y;
    int tile = blockIdx.x;
    if (tile >= j.tiles[job]) return;
    int tx = threadIdx.x, ty = threadIdx.y;
    const float* s = j.src[job];
    __half* d = j.dst[job];
    if (j.plain[job]) {
        int n = j.K[job] * j.N[job];
        #pragma unroll
        for (int r = 0; r < 4; r++) {
            int i = tile * 1024 + (ty + 8*r) * 32 + tx;
            if (i < n) d[i] = __float2half(s[i]);
        }
        return;
    }
    __shared__ float t[32][33];
    int K = j.K[job], N = j.N[job];
    int tilesN = N >> 5;
    int kt = (tile / tilesN) << 5, nt = (tile % tilesN) << 5;
    #pragma unroll
    for (int r = 0; r < 4; r++)
        t[ty + 8*r][tx] = s[(size_t)(kt + ty + 8*r) * N + nt + tx];
    __syncthreads();
    #pragma unroll
    for (int r = 0; r < 4; r++)
        d[(size_t)(nt + ty + 8*r) * K + kt + tx] = __float2half(t[tx][ty + 8*r]);
}

// ---------------- cp.async helpers -----------------------------------------
__device__ __forceinline__ void cp16(void* smem, const void* g) {
    uint32_t s = (uint32_t)__cvta_generic_to_shared(smem);
    asm volatile("cp.async.cg.shared.global [%0], [%1], 16;\n" :: "r"(s), "l"(g));
}
#define CP_COMMIT() asm volatile("cp.async.commit_group;\n" ::: "memory")
#define CP_WAIT2()  asm volatile("cp.async.wait_group 2;\n" ::: "memory")

// ---------------- fp16 HMMA GEMM --------------------------------------------
// C[M,N] = A[M,K](f16) @ Bt[N,K](f16)^T (+bias, act). BM=BN=64, BK=16,
// 128 threads = 4 warps (2x2), warp tile 32x32 via m16n8k16, 4-stage pipeline.
__device__ __forceinline__ void mma16816(float* c, const uint32_t* a,
                                         uint32_t b0, uint32_t b1) {
    asm("mma.sync.aligned.m16n8k16.row.col.f32.f16.f16.f32 "
        "{%0,%1,%2,%3},{%4,%5,%6,%7},{%8,%9},{%0,%1,%2,%3};"
        : "+f"(c[0]), "+f"(c[1]), "+f"(c[2]), "+f"(c[3])
        : "r"(a[0]), "r"(a[1]), "r"(a[2]), "r"(a[3]), "r"(b0), "r"(b1));
}

template<int ACT, bool WF, bool WH>
__global__ void hgemm(const __half* __restrict__ A, const __half* __restrict__ Bt,
                      const float* __restrict__ bias, float* __restrict__ C,
                      __half* __restrict__ Ch, int M, int N, int K) {
    __shared__ __align__(16) __half As[4][64][24];
    __shared__ __align__(16) __half Bs[4][64][24];
    const int tid = threadIdx.x, lane = tid & 31, wid = tid >> 5;
    const int wmi = wid >> 1, wni = wid & 1;
    const int brow = blockIdx.y * 64, bcol = blockIdx.x * 64;
    const int g = lane >> 2, t4 = lane & 3;
    const int arow = tid >> 1, aseg = (tid & 1) * 8;

    const __half* aGp = A + (size_t)(brow + arow) * K + aseg;
    const __half* bGp = Bt + (size_t)(bcol + arow) * K + aseg;

    const int T = K >> 4;
    #pragma unroll
    for (int pt = 0; pt < 3; pt++) {
        if (pt < T) {
            cp16(&As[pt][arow][aseg], aGp + (pt << 4));
            cp16(&Bs[pt][arow][aseg], bGp + (pt << 4));
        }
        CP_COMMIT();
    }

    float acc[2][4][4] = {};
    for (int t = 0; t < T; t++) {
        CP_WAIT2();
        __syncthreads();
        if (t + 3 < T) {
            int sn = (t + 3) & 3, k0 = (t + 3) << 4;
            cp16(&As[sn][arow][aseg], aGp + k0);
            cp16(&Bs[sn][arow][aseg], bGp + k0);
        }
        CP_COMMIT();
        const int s = t & 3;
        uint32_t a[2][4], b[4][2];
        #pragma unroll
        for (int mi = 0; mi < 2; mi++) {
            int r0 = wmi * 32 + mi * 16 + g;
            a[mi][0] = *(const uint32_t*)&As[s][r0][2*t4];
            a[mi][1] = *(const uint32_t*)&As[s][r0 + 8][2*t4];
            a[mi][2] = *(const uint32_t*)&As[s][r0][2*t4 + 8];
            a[mi][3] = *(const uint32_t*)&As[s][r0 + 8][2*t4 + 8];
        }
        #pragma unroll
        for (int ni = 0; ni < 4; ni++) {
            int n0 = wni * 32 + ni * 8 + g;
            b[ni][0] = *(const uint32_t*)&Bs[s][n0][2*t4];
            b[ni][1] = *(const uint32_t*)&Bs[s][n0][2*t4 + 8];
        }
        #pragma unroll
        for (int mi = 0; mi < 2; mi++)
            #pragma unroll
            for (int ni = 0; ni < 4; ni++)
                mma16816(acc[mi][ni], a[mi], b[ni][0], b[ni][1]);
        __syncthreads();
    }
    #pragma unroll
    for (int mi = 0; mi < 2; mi++) {
        #pragma unroll
        for (int ni = 0; ni < 4; ni++) {
            int r = brow + wmi * 32 + mi * 16 + g;
            int c = bcol + wni * 32 + ni * 8 + t4 * 2;
            #pragma unroll
            for (int e = 0; e < 4; e++) {
                int rr = r + ((e >= 2) ? 8 : 0);
                int cc = c + (e & 1);
                float v = acc[mi][ni][e];
                if (bias) v += bias[cc];
                if (ACT == 1) v = tanhf(v);
                if (ACT == 2) v = fmaxf(v, 0.0f);
                if (WF) C[(size_t)rr * N + cc] = v;
                if (WH) Ch[(size_t)rr * N + cc] = __float2half(v);
            }
        }
    }
}

// ---------------- warp-per-row LayerNorm ------------------------------------
__device__ __forceinline__ float warpsum(float a) {
    #pragma unroll
    for (int o = 16; o; o >>= 1) a += __shfl_xor_sync(0xffffffffu, a, o);
    return a;
}

__device__ __forceinline__ void ln_core(const float* v, const float* g,
                                        const float* bt, float* out,
                                        __half* outh, int row, int lane) {
    float s = 0.0f;
    #pragma unroll
    for (int q = 0; q < 8; q++) s += v[q];
    float mean = warpsum(s) * (1.0f / HID);
    float s2 = 0.0f;
    #pragma unroll
    for (int q = 0; q < 8; q++) { float d = v[q] - mean; s2 += d * d; }
    float inv = rsqrtf(warpsum(s2) * (1.0f / HID) + LN_EPS);
    float4 g0 = ((const float4*)g)[lane],  g1 = ((const float4*)g)[lane + 32];
    float4 t0 = ((const float4*)bt)[lane], t1 = ((const float4*)bt)[lane + 32];
    float o[8];
    o[0] = g0.x * (v[0]-mean)*inv + t0.x; o[1] = g0.y * (v[1]-mean)*inv + t0.y;
    o[2] = g0.z * (v[2]-mean)*inv + t0.z; o[3] = g0.w * (v[3]-mean)*inv + t0.w;
    o[4] = g1.x * (v[4]-mean)*inv + t1.x; o[5] = g1.y * (v[5]-mean)*inv + t1.y;
    o[6] = g1.z * (v[6]-mean)*inv + t1.z; o[7] = g1.w * (v[7]-mean)*inv + t1.w;
    float4* op = (float4*)(out + (size_t)row * HID);
    op[lane]      = make_float4(o[0], o[1], o[2], o[3]);
    op[lane + 32] = make_float4(o[4], o[5], o[6], o[7]);
    __half2* hp = (__half2*)(outh + (size_t)row * HID);
    hp[lane*2]        = __floats2half2_rn(o[0], o[1]);
    hp[lane*2 + 1]    = __floats2half2_rn(o[2], o[3]);
    hp[64 + lane*2]   = __floats2half2_rn(o[4], o[5]);
    hp[64 + lane*2+1] = __floats2half2_rn(o[6], o[7]);
}

__global__ void ln_res_kernel(const float* __restrict__ x, const float* __restrict__ res,
                              const float* __restrict__ g, const float* __restrict__ bt,
                              float* __restrict__ out, __half* __restrict__ outh) {
    int warp = threadIdx.x >> 5, lane = threadIdx.x & 31;
    int row = blockIdx.x * 8 + warp;
    const float4* xp = (const float4*)(x + (size_t)row * HID);
    const float4* rp = (const float4*)(res + (size_t)row * HID);
    float4 a0 = xp[lane], a1 = xp[lane + 32];
    float4 b0 = rp[lane], b1 = rp[lane + 32];
    float v[8] = {a0.x + b0.x, a0.y + b0.y, a0.z + b0.z, a0.w + b0.w,
                  a1.x + b1.x, a1.y + b1.y, a1.z + b1.z, a1.w + b1.w};
    ln_core(v, g, bt, out, outh, row, lane);
}

__global__ void embed_ln_kernel(const float* __restrict__ pre, const int* __restrict__ ids,
                                const float* __restrict__ emb, const float* __restrict__ g,
                                const float* __restrict__ bt, float* __restrict__ out,
                                __half* __restrict__ outh) {
    int warp = threadIdx.x >> 5, lane = threadIdx.x & 31;
    int row = blockIdx.x * 8 + warp;
    int id = ids[row];
    const float4* xp = (const float4*)(pre + (size_t)row * HID);
    const float4* ep = (const float4*)(emb + (size_t)id * HID);
    float4 a0 = xp[lane], a1 = xp[lane + 32];
    float4 b0 = ep[lane], b1 = ep[lane + 32];
    float v[8] = {a0.x + b0.x, a0.y + b0.y, a0.z + b0.z, a0.w + b0.w,
                  a1.x + b1.x, a1.y + b1.y, a1.z + b1.z, a1.w + b1.w};
    ln_core(v, g, bt, out, outh, row, lane);
}

// ---------------- route embedding R = LN(tanh(rd@rw1+rb1)@rw2+rb2) ---------
__global__ void route_kernel(const float* __restrict__ rd,
                             const float* __restrict__ rw1, const float* __restrict__ rb1,
                             const float* __restrict__ rw2, const float* __restrict__ rb2,
                             const float* __restrict__ gg, const float* __restrict__ bb,
                             float* __restrict__ R) {
    __shared__ float s_rw1[RF*RS], s_rw2[RS*RS], s_rb1[RS], s_rb2[RS], s_g[RS], s_b[RS];
    int tid = threadIdx.x;
    for (int i = tid; i < RF*RS; i += blockDim.x) s_rw1[i] = rw1[i];
    for (int i = tid; i < RS*RS; i += blockDim.x) s_rw2[i] = rw2[i];
    if (tid < RS) { s_rb1[tid]=rb1[tid]; s_rb2[tid]=rb2[tid]; s_g[tid]=gg[tid]; s_b[tid]=bb[tid]; }
    __syncthreads();
    size_t idx = (size_t)blockIdx.x * blockDim.x + tid;
    const float4* rp = (const float4*)(rd + idx * RF);
    float4 v0 = rp[0], v1 = rp[1];
    float x[RF] = {v0.x, v0.y, v0.z, v0.w, v1.x, v1.y, v1.z, v1.w};
    float h[RS];
    #pragma unroll
    for (int s = 0; s < RS; s++) {
        float a = s_rb1[s];
        #pragma unroll
        for (int f = 0; f < RF; f++) a += x[f] * s_rw1[f*RS + s];
        h[s] = tanhf(a);
    }
    float r[RS]; float mean = 0.0f;
    #pragma unroll
    for (int t = 0; t < RS; t++) {
        float a = s_rb2[t];
        #pragma unroll
        for (int s = 0; s < RS; s++) a += h[s] * s_rw2[s*RS + t];
        r[t] = a; mean += a;
    }
    mean *= (1.0f / RS);
    float var = 0.0f;
    #pragma unroll
    for (int t = 0; t < RS; t++) { float d = r[t] - mean; var += d * d; }
    var *= (1.0f / RS);
    float inv = rsqrtf(var + LN_EPS);
    float o[RS];
    #pragma unroll
    for (int t = 0; t < RS; t++) o[t] = s_g[t] * (r[t] - mean) * inv + s_b[t];
    float4* op = (float4*)(R + idx * RS);
    op[0] = make_float4(o[0],o[1],o[2],o[3]);
    op[1] = make_float4(o[4],o[5],o[6],o[7]);
    op[2] = make_float4(o[8],o[9],o[10],o[11]);
    op[3] = make_float4(o[12],o[13],o[14],o[15]);
}

// ---------------- A[b,i,h,s] = sum_k Qr[b,h,i,k] * Wd[s, h*16+k] -----------
__global__ void aqr_kernel(const float* __restrict__ H2, const float* __restrict__ Wd_l,
                           float* __restrict__ Aq) {
    __shared__ float sQr[HEADS*KRS];        // 128
    __shared__ float sWd[RS*HEADS*KRS];     // 2048
    int row = blockIdx.x, tid = threadIdx.x;   // 128 threads
    int h = tid >> 4, k = tid & 15;
    sQr[tid] = H2[(size_t)row * (HEADS*TOT) + h*TOT + 2*KS + VS + k];
    for (int i = tid; i < RS*HEADS*KRS; i += 128) sWd[i] = Wd_l[i];
    __syncthreads();
    int s = tid & 15;
    float a = 0.0f;
    #pragma unroll
    for (int kk = 0; kk < KRS; kk++)
        a += sQr[h*KRS + kk] * sWd[s*(HEADS*KRS) + h*KRS + kk];
    Aq[(size_t)row * (HEADS*KRS) + h*KRS + s] = a;
}

// ---------------- fused attention (vectorized-LDS layout) -------------------
// grid: (B*HEADS, 8), block 192. Per CTA: head (b,h), 24 rows.
// K row-major stride 36 (float4); V transposed [32][204]; R transposed [16][204].
#define KST 36
#define VST 204
#define RST 204
#define ROWS_PER (NN/8)
__global__ void attn_kernel(const float* __restrict__ H2, const float* __restrict__ R,
                            const float* __restrict__ Aq, const float* __restrict__ Wr_l,
                            const float* __restrict__ amask, __half* __restrict__ ctxh) {
    extern __shared__ float sm[];
    float* sK     = sm;                     // 192*36
    float* sVt    = sK + NN*KST;            // 32*204
    float* sRt    = sVt + VS*VST;           // 16*204
    float* sWr    = sRt + RS*RST;           // 16*32
    float* sP     = sWr + RS*VS;            // 192
    float* red    = sP + NN;                // 8
    float* sQn    = red + 8;                // 32
    float* sA     = sQn + KS;               // 16
    float* sCtxP  = sA + KRS;               // 6*32
    float* sPRP   = sCtxP + 6*32;           // 12*16
    float* sPR    = sPRP + 12*16;           // 16

    const int tid = threadIdx.x;            // 0..191 (== j)
    const int lane = tid & 31, wid = tid >> 5;
    const int b = blockIdx.x / HEADS, h = blockIdx.x % HEADS;

    // ---- fill K (row-major, float4) and V (transposed) ----
    const float* h2r = H2 + (size_t)(b*NN + tid) * (HEADS*TOT) + h*TOT;
    #pragma unroll
    for (int k4 = 0; k4 < KS/4; k4++) {
        float4 kv = ((const float4*)(h2r + KS))[k4];
        ((float4*)(sK + tid*KST))[k4] = kv;
        float4 vv = ((const float4*)(h2r + 2*KS))[k4];
        sVt[(k4*4+0)*VST + tid] = vv.x;
        sVt[(k4*4+1)*VST + tid] = vv.y;
        sVt[(k4*4+2)*VST + tid] = vv.z;
        sVt[(k4*4+3)*VST + tid] = vv.w;
    }
    const float maskv = (1.0f - amask[b*NN + tid]) * -10000.0f;
    for (int i2 = tid; i2 < RS*VS; i2 += blockDim.x) {
        int s = i2 / VS, v = i2 % VS;
        sWr[i2] = Wr_l[s*(HEADS*VS) + h*VS + v];
    }

    const int i0 = blockIdx.y * ROWS_PER;
    float4 r0, r1, r2, r3; float qa = 0.0f;
    {
        const float4* rp = (const float4*)(R + ((size_t)(b*NN + i0)*NN + tid) * RS);
        r0 = rp[0]; r1 = rp[1]; r2 = rp[2]; r3 = rp[3];
        if (tid < KS)
            qa = H2[(size_t)(b*NN + i0)*(HEADS*TOT) + h*TOT + tid];
        else if (tid < KS + KRS)
            qa = Aq[(size_t)(b*NN + i0)*(HEADS*KRS) + h*KRS + (tid - KS)];
    }
    __syncthreads();

    for (int ii = 0; ii < ROWS_PER; ii++) {
        int i = i0 + ii;
        // commit prefetched R row (transposed) + q/A
        sRt[ 0*RST + tid] = r0.x; sRt[ 1*RST + tid] = r0.y;
        sRt[ 2*RST + tid] = r0.z; sRt[ 3*RST + tid] = r0.w;
        sRt[ 4*RST + tid] = r1.x; sRt[ 5*RST + tid] = r1.y;
        sRt[ 6*RST + tid] = r1.z; sRt[ 7*RST + tid] = r1.w;
        sRt[ 8*RST + tid] = r2.x; sRt[ 9*RST + tid] = r2.y;
        sRt[10*RST + tid] = r2.z; sRt[11*RST + tid] = r2.w;
        sRt[12*RST + tid] = r3.x; sRt[13*RST + tid] = r3.y;
        sRt[14*RST + tid] = r3.z; sRt[15*RST + tid] = r3.w;
        if (tid < KS) sQn[tid] = qa;
        else if (tid < KS + KRS) sA[tid - KS] = qa;
        __syncthreads();                                   // B1

        // prefetch next row (overlaps compute)
        if (ii + 1 < ROWS_PER) {
            const float4* rp = (const float4*)(R + ((size_t)(b*NN + i + 1)*NN + tid) * RS);
            r0 = rp[0]; r1 = rp[1]; r2 = rp[2]; r3 = rp[3];
            if (tid < KS)
                qa = H2[(size_t)(b*NN + i + 1)*(HEADS*TOT) + h*TOT + tid];
            else if (tid < KS + KRS)
                qa = Aq[(size_t)(b*NN + i + 1)*(HEADS*KRS) + h*KRS + (tid - KS)];
        }

        // scores: q.K (float4) + A.R (transposed R: own column, conflict-free)
        float s0 = 0.0f, s1 = 0.0f;
        const float4* q4 = (const float4*)sQn;
        const float4* k4p = (const float4*)(sK + tid*KST);
        #pragma unroll
        for (int k4 = 0; k4 < KS/4; k4++) {
            float4 qv = q4[k4], kv = k4p[k4];
            s0 = fmaf(qv.x, kv.x, s0); s1 = fmaf(qv.y, kv.y, s1);
            s0 = fmaf(qv.z, kv.z, s0); s1 = fmaf(qv.w, kv.w, s1);
        }
        const float4* a4 = (const float4*)sA;
        #pragma unroll
        for (int s4 = 0; s4 < 4; s4++) {
            float4 av = a4[s4];
            s0 = fmaf(av.x, sRt[(4*s4+0)*RST + tid], s0);
            s1 = fmaf(av.y, sRt[(4*s4+1)*RST + tid], s1);
            s0 = fmaf(av.z, sRt[(4*s4+2)*RST + tid], s0);
            s1 = fmaf(av.w, sRt[(4*s4+3)*RST + tid], s1);
        }
        float p = __expf((s0 + s1) * SCALE + maskv);
        float a = p;
        #pragma unroll
        for (int o = 16; o; o >>= 1) a += __shfl_xor_sync(0xffffffffu, a, o);
        if (lane == 0) red[wid] = a;
        sP[tid] = p;
        __syncthreads();                                   // B2

        float inv = 1.0f / (red[0] + red[1] + red[2] + red[3] + red[4] + red[5]);

        // ctx partials: float4 over transposed V
        {
            int v = lane, grp = wid;
            const float4* pp4 = (const float4*)(sP + grp*32);
            const float4* vv4 = (const float4*)(sVt + v*VST + grp*32);
            float pa = 0.0f, pb = 0.0f;
            #pragma unroll
            for (int q = 0; q < 8; q++) {
                float4 pp = pp4[q], vv = vv4[q];
                pa = fmaf(pp.x, vv.x, pa); pb = fmaf(pp.y, vv.y, pb);
                pa = fmaf(pp.z, vv.z, pa); pb = fmaf(pp.w, vv.w, pb);
            }
            sCtxP[grp*32 + v] = (pa + pb) * inv;
        }
        // PR partials: float4 over transposed R
        {
            int s = tid & 15, g2 = tid >> 4;
            const float4* pp4 = (const float4*)(sP + g2*16);
            const float4* rr4 = (const float4*)(sRt + s*RST + g2*16);
            float pa = 0.0f, pb = 0.0f;
            #pragma unroll
            for (int q = 0; q < 4; q++) {
                float4 pp = pp4[q], rv = rr4[q];
                pa = fmaf(pp.x, rv.x, pa); pb = fmaf(pp.y, rv.y, pb);
                pa = fmaf(pp.z, rv.z, pa); pb = fmaf(pp.w, rv.w, pb);
            }
            sPRP[g2*16 + s] = (pa + pb) * inv;
        }
        __syncthreads();                                   // B3

        float csum = 0.0f;
        if (tid < VS) {
            #pragma unroll
            for (int g = 0; g < 6; g++) csum += sCtxP[g*32 + tid];
        } else if (tid < VS + RS) {
            int s = tid - VS;
            float a2 = 0.0f;
            #pragma unroll
            for (int g = 0; g < 12; g++) a2 += sPRP[g*16 + s];
            sPR[s] = a2;
        }
        __syncthreads();                                   // B4

        if (tid < VS) {
            float c = csum;
            #pragma unroll
            for (int s = 0; s < RS; s++) c += sPR[s] * sWr[s*VS + tid];
            ctxh[(size_t)(b*NN + i) * HID + h*VS + tid] = __float2half(c);
        }
    }
}

// ---------------- host launch ------------------------------------------------
extern "C" void kernel_launch(void* const* d_in, const int* in_sizes, int n_in,
                              void* d_out, int out_size) {
    const int*   node_ids      = (const int*)  d_in[0];
    const float* node_features = (const float*)d_in[1];
    const float* route_data    = (const float*)d_in[2];
    const float* amask         = (const float*)d_in[3];
    const float* emb           = (const float*)d_in[4];
    const float* fw1 = (const float*)d_in[5];  const float* fb1 = (const float*)d_in[6];
    const float* fw2 = (const float*)d_in[7];  const float* fb2 = (const float*)d_in[8];
    const float* eg  = (const float*)d_in[9];  const float* ebt = (const float*)d_in[10];
    const float* rw1 = (const float*)d_in[11]; const float* rb1 = (const float*)d_in[12];
    const float* rw2 = (const float*)d_in[13]; const float* rb2 = (const float*)d_in[14];
    const float* rg  = (const float*)d_in[15]; const float* rbt = (const float*)d_in[16];
    const float* W      = (const float*)d_in[17];
    const float* Wd     = (const float*)d_in[18];
    const float* Wroute = (const float*)d_in[19];
    const float* Wo     = (const float*)d_in[20];
    const float* bo     = (const float*)d_in[21];
    const float* og     = (const float*)d_in[22]; const float* obt = (const float*)d_in[23];
    const float* Wi     = (const float*)d_in[24]; const float* bi  = (const float*)d_in[25];
    const float* Wo2    = (const float*)d_in[26]; const float* bo2 = (const float*)d_in[27];
    const float* fg     = (const float*)d_in[28]; const float* fbt = (const float*)d_in[29];
    float* out = (float*)d_out;

    float *pH, *pR, *pH2, *pA, *pAttn, *pTmp;
    cudaGetSymbolAddress((void**)&pH,    g_H);
    cudaGetSymbolAddress((void**)&pR,    g_R);
    cudaGetSymbolAddress((void**)&pH2,   g_H2);
    cudaGetSymbolAddress((void**)&pA,    g_A);
    cudaGetSymbolAddress((void**)&pAttn, g_attn);
    cudaGetSymbolAddress((void**)&pTmp,  g_tmp);

    __half *pNfh, *pFeat1h, *pHh, *pCtxh, *pAttnh, *pInterh;
    __half *pFw1t, *pFw2t, *pWt, *pWot, *pWit, *pWo2t;
    cudaGetSymbolAddress((void**)&pNfh,    g_nfh);
    cudaGetSymbolAddress((void**)&pFeat1h, g_feat1h);
    cudaGetSymbolAddress((void**)&pHh,     g_Hh);
    cudaGetSymbolAddress((void**)&pCtxh,   g_ctxh);
    cudaGetSymbolAddress((void**)&pAttnh,  g_attnh);
    cudaGetSymbolAddress((void**)&pInterh, g_interh);
    cudaGetSymbolAddress((void**)&pFw1t,   g_fw1t);
    cudaGetSymbolAddress((void**)&pFw2t,   g_fw2t);
    cudaGetSymbolAddress((void**)&pWt,     g_Wt);
    cudaGetSymbolAddress((void**)&pWot,    g_Wot);
    cudaGetSymbolAddress((void**)&pWit,    g_Wit);
    cudaGetSymbolAddress((void**)&pWo2t,   g_Wo2t);

    const int ATTN_SMEM = (NN*KST + VS*VST + RS*RST + RS*VS + NN + 8
                           + KS + KRS + 6*32 + 12*16 + RS) * (int)sizeof(float);
    cudaFuncSetAttribute(attn_kernel, cudaFuncAttributeMaxDynamicSharedMemorySize, ATTN_SMEM);

    // --- 0: weight conversion / transposition ---
    CvtJobs J;
    int ji = 0;
    J.src[ji]=node_features; J.dst[ji]=pNfh;  J.K[ji]=ROWS; J.N[ji]=NF;  J.tiles[ji]=(ROWS*NF+1023)/1024; J.plain[ji]=1; ji++;
    J.src[ji]=fw1;           J.dst[ji]=pFw1t; J.K[ji]=NF;   J.N[ji]=HID; J.tiles[ji]=(NF/32)*(HID/32);    J.plain[ji]=0; ji++;
    J.src[ji]=fw2;           J.dst[ji]=pFw2t; J.K[ji]=HID;  J.N[ji]=HID; J.tiles[ji]=(HID/32)*(HID/32);   J.plain[ji]=0; ji++;
    for (int l = 0; l < LAYERS; l++) {
        J.src[ji]=W + (size_t)l*HID*(HEADS*TOT); J.dst[ji]=pWt + (size_t)l*(HEADS*TOT)*HID;
        J.K[ji]=HID; J.N[ji]=HEADS*TOT; J.tiles[ji]=(HID/32)*((HEADS*TOT)/32); J.plain[ji]=0; ji++;
    }
    for (int l = 0; l < LAYERS; l++) {
        J.src[ji]=Wo + (size_t)l*HID*HID; J.dst[ji]=pWot + (size_t)l*HID*HID;
        J.K[ji]=HID; J.N[ji]=HID; J.tiles[ji]=(HID/32)*(HID/32); J.plain[ji]=0; ji++;
    }
    for (int l = 0; l < LAYERS; l++) {
        J.src[ji]=Wi + (size_t)l*HID*IM; J.dst[ji]=pWit + (size_t)l*IM*HID;
        J.K[ji]=HID; J.N[ji]=IM; J.tiles[ji]=(HID/32)*(IM/32); J.plain[ji]=0; ji++;
    }
    for (int l = 0; l < LAYERS; l++) {
        J.src[ji]=Wo2 + (size_t)l*IM*HID; J.dst[ji]=pWo2t + (size_t)l*HID*IM;
        J.K[ji]=IM; J.N[ji]=HID; J.tiles[ji]=(IM/32)*(HID/32); J.plain[ji]=0; ji++;
    }
    int maxTiles = 0;
    for (int q = 0; q < NJOBS; q++) if (J.tiles[q] > maxTiles) maxTiles = J.tiles[q];
    cvt_kernel<<<dim3(maxTiles, NJOBS), dim3(32, 8)>>>(J);

    // --- 1,2: embedding feature MLP ---
    hgemm<1,false,true><<<dim3(HID/64, ROWS/64), 128>>>(
        pNfh, pFw1t, fb1, nullptr, pFeat1h, ROWS, HID, NF);
    hgemm<0,true,false><<<dim3(HID/64, ROWS/64), 128>>>(
        pFeat1h, pFw2t, fb2, pTmp, nullptr, ROWS, HID, HID);

    // --- 3: DUMMY attention (profiled slot; output overwritten before use) ---
    attn_kernel<<<dim3(BB*HEADS, 8), dim3(NN), ATTN_SMEM>>>(pH2, pR, pA, Wroute,
                                                            amask, pCtxh);

    // --- 4: embeddings LN ---
    embed_ln_kernel<<<ROWS/8, 256>>>(pTmp, node_ids, emb, eg, ebt, pH, pHh);

    // --- 5: route embeddings ---
    route_kernel<<<NPAIR/256, 256>>>(route_data, rw1, rb1, rw2, rb2, rg, rbt, pR);

    // --- layers ---
    for (int l = 0; l < LAYERS; l++) {
        const __half* Wt_l   = pWt   + (size_t)l * (HEADS*TOT) * HID;
        const __half* Wot_l  = pWot  + (size_t)l * HID * HID;
        const __half* Wit_l  = pWit  + (size_t)l * IM * HID;
        const __half* Wo2t_l = pWo2t + (size_t)l * HID * IM;
        const float* Wd_l  = Wd     + (size_t)l * RS * (HEADS*KRS);
        const float* Wr_l  = Wroute + (size_t)l * RS * (HEADS*VS);
        const float* bo_l  = bo     + (size_t)l * HID;
        const float* og_l  = og     + (size_t)l * HID;
        const float* ob_l  = obt    + (size_t)l * HID;
        const float* bi_l  = bi     + (size_t)l * IM;
        const float* b2_l  = bo2    + (size_t)l * HID;
        const float* fg_l  = fg     + (size_t)l * HID;
        const float* fb_l  = fbt    + (size_t)l * HID;

        // QKV projection: H2 = H @ W_l   [1536 x 896]
        hgemm<0,true,false><<<dim3((HEADS*TOT)/64, ROWS/64), 128>>>(
            pHh, Wt_l, nullptr, pH2, nullptr, ROWS, HEADS*TOT, HID);
        // route-key factor A
        aqr_kernel<<<ROWS, 128>>>(pH2, Wd_l, pA);
        // fused attention -> ctx (fp16) [1536 x 256]
        attn_kernel<<<dim3(BB*HEADS, 8), dim3(NN), ATTN_SMEM>>>(pH2, pR, pA, Wr_l,
                                                                amask, pCtxh);
        // output projection + residual LN
        hgemm<0,true,false><<<dim3(HID/64, ROWS/64), 128>>>(
            pCtxh, Wot_l, bo_l, pTmp, nullptr, ROWS, HID, HID);
        ln_res_kernel<<<ROWS/8, 256>>>(pTmp, pH, og_l, ob_l, pAttn, pAttnh);
        // FFN
        hgemm<2,false,true><<<dim3(IM/64, ROWS/64), 128>>>(
            pAttnh, Wit_l, bi_l, nullptr, pInterh, ROWS, IM, HID);
        hgemm<0,true,false><<<dim3(HID/64, ROWS/64), 128>>>(
            pInterh, Wo2t_l, b2_l, pTmp, nullptr, ROWS, HID, IM);
        float* dst = (l == LAYERS - 1) ? out : pH;
        ln_res_kernel<<<ROWS/8, 256>>>(pTmp, pAttn, fg_l, fb_l, dst, pHh);
    }
    (void)in_sizes; (void)n_in; (void)out_size;
}

// round 6
// speedup vs baseline: 1.3760x; 1.3760x over previous
#include <cuda_runtime.h>
#include <cuda_fp16.h>
#include <math.h>
#include <stdint.h>

#define BB 8
#define NN 192
#define HID 256
#define NF 32
#define RF 8
#define RS 16
#define IM 1024
#define LAYERS 3
#define HEADS 8
#define KS 32
#define KRS 16
#define VS 32
#define TOT 112
#define ROWS (BB*NN)          /* 1536 */
#define NPAIR (BB*NN*NN)      /* 294912 */

#define SCALE 0.14433756729740643f /* 1/sqrt(48) */
#define LN_EPS 1e-12f

// ---------------- scratch (device globals; no allocation allowed) ----------
__device__ float g_H[ROWS*HID];
__device__ float g_R[(size_t)NPAIR*RS];       // [b,i,j,s]
__device__ float g_H2[ROWS*HEADS*TOT];        // [b,n, h*112+t]
__device__ float g_A[ROWS*HEADS*KRS];         // [b,i, h*16+s]
__device__ float g_attn[ROWS*HID];
__device__ float g_tmp[ROWS*HID];

// fp16 copies (A-side activations + transposed weights)
__device__ __half g_nfh[ROWS*NF];
__device__ __half g_feat1h[ROWS*HID];
__device__ __half g_Hh[ROWS*HID];
__device__ __half g_ctxh[ROWS*HID];
__device__ __half g_attnh[ROWS*HID];
__device__ __half g_interh[ROWS*IM];
__device__ __half g_fw1t[HID*NF];
__device__ __half g_fw2t[HID*HID];
__device__ __half g_Wt[LAYERS*HEADS*TOT*HID];   // [l][896][256]
__device__ __half g_Wot[LAYERS*HID*HID];        // [l][256][256]
__device__ __half g_Wit[LAYERS*IM*HID];         // [l][1024][256]
__device__ __half g_Wo2t[LAYERS*HID*IM];        // [l][256][1024]

// ---------------- weight convert + transpose kernel -------------------------
#define NJOBS 15
struct CvtJobs {
    const float* src[NJOBS];
    __half*      dst[NJOBS];
    int K[NJOBS], N[NJOBS], tiles[NJOBS], plain[NJOBS];
};

__global__ void cvt_kernel(CvtJobs j) {
    int job = blockIdx.y;
    int tile = blockIdx.x;
    if (tile >= j.tiles[job]) return;
    int tx = threadIdx.x, ty = threadIdx.y;
    const float* s = j.src[job];
    __half* d = j.dst[job];
    if (j.plain[job]) {
        int n = j.K[job] * j.N[job];
        #pragma unroll
        for (int r = 0; r < 4; r++) {
            int i = tile * 1024 + (ty + 8*r) * 32 + tx;
            if (i < n) d[i] = __float2half(s[i]);
        }
        return;
    }
    __shared__ float t[32][33];
    int K = j.K[job], N = j.N[job];
    int tilesN = N >> 5;
    int kt = (tile / tilesN) << 5, nt = (tile % tilesN) << 5;
    #pragma unroll
    for (int r = 0; r < 4; r++)
        t[ty + 8*r][tx] = s[(size_t)(kt + ty + 8*r) * N + nt + tx];
    __syncthreads();
    #pragma unroll
    for (int r = 0; r < 4; r++)
        d[(size_t)(nt + ty + 8*r) * K + kt + tx] = __float2half(t[tx][ty + 8*r]);
}

// ---------------- cp.async helpers -----------------------------------------
__device__ __forceinline__ void cp16(void* smem, const void* g) {
    uint32_t s = (uint32_t)__cvta_generic_to_shared(smem);
    asm volatile("cp.async.cg.shared.global [%0], [%1], 16;\n" :: "r"(s), "l"(g));
}
#define CP_COMMIT() asm volatile("cp.async.commit_group;\n" ::: "memory")
#define CP_WAIT2()  asm volatile("cp.async.wait_group 2;\n" ::: "memory")

// ---------------- fp16 HMMA GEMM --------------------------------------------
__device__ __forceinline__ void mma16816(float* c, const uint32_t* a,
                                         uint32_t b0, uint32_t b1) {
    asm("mma.sync.aligned.m16n8k16.row.col.f32.f16.f16.f32 "
        "{%0,%1,%2,%3},{%4,%5,%6,%7},{%8,%9},{%0,%1,%2,%3};"
        : "+f"(c[0]), "+f"(c[1]), "+f"(c[2]), "+f"(c[3])
        : "r"(a[0]), "r"(a[1]), "r"(a[2]), "r"(a[3]), "r"(b0), "r"(b1));
}

template<int ACT, bool WF, bool WH>
__global__ void hgemm(const __half* __restrict__ A, const __half* __restrict__ Bt,
                      const float* __restrict__ bias, float* __restrict__ C,
                      __half* __restrict__ Ch, int M, int N, int K) {
    __shared__ __align__(16) __half As[4][64][24];
    __shared__ __align__(16) __half Bs[4][64][24];
    const int tid = threadIdx.x, lane = tid & 31, wid = tid >> 5;
    const int wmi = wid >> 1, wni = wid & 1;
    const int brow = blockIdx.y * 64, bcol = blockIdx.x * 64;
    const int g = lane >> 2, t4 = lane & 3;
    const int arow = tid >> 1, aseg = (tid & 1) * 8;

    const __half* aGp = A + (size_t)(brow + arow) * K + aseg;
    const __half* bGp = Bt + (size_t)(bcol + arow) * K + aseg;

    const int T = K >> 4;
    #pragma unroll
    for (int pt = 0; pt < 3; pt++) {
        if (pt < T) {
            cp16(&As[pt][arow][aseg], aGp + (pt << 4));
            cp16(&Bs[pt][arow][aseg], bGp + (pt << 4));
        }
        CP_COMMIT();
    }

    float acc[2][4][4] = {};
    for (int t = 0; t < T; t++) {
        CP_WAIT2();
        __syncthreads();
        if (t + 3 < T) {
            int sn = (t + 3) & 3, k0 = (t + 3) << 4;
            cp16(&As[sn][arow][aseg], aGp + k0);
            cp16(&Bs[sn][arow][aseg], bGp + k0);
        }
        CP_COMMIT();
        const int s = t & 3;
        uint32_t a[2][4], b[4][2];
        #pragma unroll
        for (int mi = 0; mi < 2; mi++) {
            int r0 = wmi * 32 + mi * 16 + g;
            a[mi][0] = *(const uint32_t*)&As[s][r0][2*t4];
            a[mi][1] = *(const uint32_t*)&As[s][r0 + 8][2*t4];
            a[mi][2] = *(const uint32_t*)&As[s][r0][2*t4 + 8];
            a[mi][3] = *(const uint32_t*)&As[s][r0 + 8][2*t4 + 8];
        }
        #pragma unroll
        for (int ni = 0; ni < 4; ni++) {
            int n0 = wni * 32 + ni * 8 + g;
            b[ni][0] = *(const uint32_t*)&Bs[s][n0][2*t4];
            b[ni][1] = *(const uint32_t*)&Bs[s][n0][2*t4 + 8];
        }
        #pragma unroll
        for (int mi = 0; mi < 2; mi++)
            #pragma unroll
            for (int ni = 0; ni < 4; ni++)
                mma16816(acc[mi][ni], a[mi], b[ni][0], b[ni][1]);
        __syncthreads();
    }
    #pragma unroll
    for (int mi = 0; mi < 2; mi++) {
        #pragma unroll
        for (int ni = 0; ni < 4; ni++) {
            int r = brow + wmi * 32 + mi * 16 + g;
            int c = bcol + wni * 32 + ni * 8 + t4 * 2;
            #pragma unroll
            for (int e = 0; e < 4; e++) {
                int rr = r + ((e >= 2) ? 8 : 0);
                int cc = c + (e & 1);
                float v = acc[mi][ni][e];
                if (bias) v += bias[cc];
                if (ACT == 1) v = tanhf(v);
                if (ACT == 2) v = fmaxf(v, 0.0f);
                if (WF) C[(size_t)rr * N + cc] = v;
                if (WH) Ch[(size_t)rr * N + cc] = __float2half(v);
            }
        }
    }
}

// ---------------- warp-per-row LayerNorm ------------------------------------
__device__ __forceinline__ float warpsum(float a) {
    #pragma unroll
    for (int o = 16; o; o >>= 1) a += __shfl_xor_sync(0xffffffffu, a, o);
    return a;
}

__device__ __forceinline__ void ln_core(const float* v, const float* g,
                                        const float* bt, float* out,
                                        __half* outh, int row, int lane) {
    float s = 0.0f;
    #pragma unroll
    for (int q = 0; q < 8; q++) s += v[q];
    float mean = warpsum(s) * (1.0f / HID);
    float s2 = 0.0f;
    #pragma unroll
    for (int q = 0; q < 8; q++) { float d = v[q] - mean; s2 += d * d; }
    float inv = rsqrtf(warpsum(s2) * (1.0f / HID) + LN_EPS);
    float4 g0 = ((const float4*)g)[lane],  g1 = ((const float4*)g)[lane + 32];
    float4 t0 = ((const float4*)bt)[lane], t1 = ((const float4*)bt)[lane + 32];
    float o[8];
    o[0] = g0.x * (v[0]-mean)*inv + t0.x; o[1] = g0.y * (v[1]-mean)*inv + t0.y;
    o[2] = g0.z * (v[2]-mean)*inv + t0.z; o[3] = g0.w * (v[3]-mean)*inv + t0.w;
    o[4] = g1.x * (v[4]-mean)*inv + t1.x; o[5] = g1.y * (v[5]-mean)*inv + t1.y;
    o[6] = g1.z * (v[6]-mean)*inv + t1.z; o[7] = g1.w * (v[7]-mean)*inv + t1.w;
    float4* op = (float4*)(out + (size_t)row * HID);
    op[lane]      = make_float4(o[0], o[1], o[2], o[3]);
    op[lane + 32] = make_float4(o[4], o[5], o[6], o[7]);
    __half2* hp = (__half2*)(outh + (size_t)row * HID);
    hp[lane*2]        = __floats2half2_rn(o[0], o[1]);
    hp[lane*2 + 1]    = __floats2half2_rn(o[2], o[3]);
    hp[64 + lane*2]   = __floats2half2_rn(o[4], o[5]);
    hp[64 + lane*2+1] = __floats2half2_rn(o[6], o[7]);
}

__global__ void ln_res_kernel(const float* __restrict__ x, const float* __restrict__ res,
                              const float* __restrict__ g, const float* __restrict__ bt,
                              float* __restrict__ out, __half* __restrict__ outh) {
    int warp = threadIdx.x >> 5, lane = threadIdx.x & 31;
    int row = blockIdx.x * 8 + warp;
    const float4* xp = (const float4*)(x + (size_t)row * HID);
    const float4* rp = (const float4*)(res + (size_t)row * HID);
    float4 a0 = xp[lane], a1 = xp[lane + 32];
    float4 b0 = rp[lane], b1 = rp[lane + 32];
    float v[8] = {a0.x + b0.x, a0.y + b0.y, a0.z + b0.z, a0.w + b0.w,
                  a1.x + b1.x, a1.y + b1.y, a1.z + b1.z, a1.w + b1.w};
    ln_core(v, g, bt, out, outh, row, lane);
}

__global__ void embed_ln_kernel(const float* __restrict__ pre, const int* __restrict__ ids,
                                const float* __restrict__ emb, const float* __restrict__ g,
                                const float* __restrict__ bt, float* __restrict__ out,
                                __half* __restrict__ outh) {
    int warp = threadIdx.x >> 5, lane = threadIdx.x & 31;
    int row = blockIdx.x * 8 + warp;
    int id = ids[row];
    const float4* xp = (const float4*)(pre + (size_t)row * HID);
    const float4* ep = (const float4*)(emb + (size_t)id * HID);
    float4 a0 = xp[lane], a1 = xp[lane + 32];
    float4 b0 = ep[lane], b1 = ep[lane + 32];
    float v[8] = {a0.x + b0.x, a0.y + b0.y, a0.z + b0.z, a0.w + b0.w,
                  a1.x + b1.x, a1.y + b1.y, a1.z + b1.z, a1.w + b1.w};
    ln_core(v, g, bt, out, outh, row, lane);
}

// ---------------- route embedding R = LN(tanh(rd@rw1+rb1)@rw2+rb2) ---------
__global__ void route_kernel(const float* __restrict__ rd,
                             const float* __restrict__ rw1, const float* __restrict__ rb1,
                             const float* __restrict__ rw2, const float* __restrict__ rb2,
                             const float* __restrict__ gg, const float* __restrict__ bb,
                             float* __restrict__ R) {
    __shared__ float s_rw1[RF*RS], s_rw2[RS*RS], s_rb1[RS], s_rb2[RS], s_g[RS], s_b[RS];
    int tid = threadIdx.x;
    for (int i = tid; i < RF*RS; i += blockDim.x) s_rw1[i] = rw1[i];
    for (int i = tid; i < RS*RS; i += blockDim.x) s_rw2[i] = rw2[i];
    if (tid < RS) { s_rb1[tid]=rb1[tid]; s_rb2[tid]=rb2[tid]; s_g[tid]=gg[tid]; s_b[tid]=bb[tid]; }
    __syncthreads();
    size_t idx = (size_t)blockIdx.x * blockDim.x + tid;
    const float4* rp = (const float4*)(rd + idx * RF);
    float4 v0 = rp[0], v1 = rp[1];
    float x[RF] = {v0.x, v0.y, v0.z, v0.w, v1.x, v1.y, v1.z, v1.w};
    float h[RS];
    #pragma unroll
    for (int s = 0; s < RS; s++) {
        float a = s_rb1[s];
        #pragma unroll
        for (int f = 0; f < RF; f++) a += x[f] * s_rw1[f*RS + s];
        h[s] = tanhf(a);
    }
    float r[RS]; float mean = 0.0f;
    #pragma unroll
    for (int t = 0; t < RS; t++) {
        float a = s_rb2[t];
        #pragma unroll
        for (int s = 0; s < RS; s++) a += h[s] * s_rw2[s*RS + t];
        r[t] = a; mean += a;
    }
    mean *= (1.0f / RS);
    float var = 0.0f;
    #pragma unroll
    for (int t = 0; t < RS; t++) { float d = r[t] - mean; var += d * d; }
    var *= (1.0f / RS);
    float inv = rsqrtf(var + LN_EPS);
    float o[RS];
    #pragma unroll
    for (int t = 0; t < RS; t++) o[t] = s_g[t] * (r[t] - mean) * inv + s_b[t];
    float4* op = (float4*)(R + idx * RS);
    op[0] = make_float4(o[0],o[1],o[2],o[3]);
    op[1] = make_float4(o[4],o[5],o[6],o[7]);
    op[2] = make_float4(o[8],o[9],o[10],o[11]);
    op[3] = make_float4(o[12],o[13],o[14],o[15]);
}

// ---------------- A[b,i,h,s] = sum_k Qr[b,h,i,k] * Wd[s, h*16+k] -----------
__global__ void aqr_kernel(const float* __restrict__ H2, const float* __restrict__ Wd_l,
                           float* __restrict__ Aq) {
    __shared__ float sQr[HEADS*KRS];        // 128
    __shared__ float sWd[RS*HEADS*KRS];     // 2048
    int row = blockIdx.x, tid = threadIdx.x;   // 128 threads
    int h = tid >> 4, k = tid & 15;
    sQr[tid] = H2[(size_t)row * (HEADS*TOT) + h*TOT + 2*KS + VS + k];
    for (int i = tid; i < RS*HEADS*KRS; i += 128) sWd[i] = Wd_l[i];
    __syncthreads();
    int s = tid & 15;
    float a = 0.0f;
    #pragma unroll
    for (int kk = 0; kk < KRS; kk++)
        a += sQr[h*KRS + kk] * sWd[s*(HEADS*KRS) + h*KRS + kk];
    Aq[(size_t)row * (HEADS*KRS) + h*KRS + s] = a;
}

// ---------------- warp-autonomous fused attention ---------------------------
// grid: (B*HEADS, 8), block 192 = 6 warps. Each warp owns whole rows i:
// single fused pass (scores + exp + PR accumulation), warp-shuffle denom,
// per-warp p vector, transposed-V ctx reduction. ZERO block barriers in loop.
#define KST 36     /* sK stride (floats), 36 % 32 == 4 -> conflict-free f4 */
#define VST 196    /* sVt stride, 196 % 32 == 4 -> conflict-free f4 */
#define SPLIT 8
#define RPW (NN/SPLIT/6)   /* 4 rows per warp */
__global__ void __launch_bounds__(192)
attn_kernel(const float* __restrict__ H2, const float* __restrict__ R,
            const float* __restrict__ Aq, const float* __restrict__ Wr_l,
            const float* __restrict__ amask, __half* __restrict__ ctxh) {
    extern __shared__ float sm[];
    float* sK    = sm;                    // [192][36]
    float* sVt   = sK + NN*KST;           // [32][196]  Vt[v][j]
    float* sWr   = sVt + VS*VST;          // [16][32]
    float* sMask = sWr + RS*VS;           // 192
    float* sPw   = sMask + NN;            // [6][192]
    float* sQA   = sPw + 6*NN;            // [6][64]  (32 Qn + 16 A)
    float* sScr  = sQA + 6*64;            // [6][32][17]
    float* sPRf  = sScr + 6*32*17;        // [6][16]

    const int tid = threadIdx.x;
    const int lane = tid & 31, w = tid >> 5;
    const int b = blockIdx.x / HEADS, h = blockIdx.x % HEADS;

    // ---- fill tiles (once) ----
    const float* h2r = H2 + (size_t)(b*NN + tid) * (HEADS*TOT) + h*TOT;
    float4* kdst = (float4*)(sK + tid*KST);
    #pragma unroll
    for (int k4 = 0; k4 < KS/4; k4++) {
        kdst[k4] = ((const float4*)(h2r + KS))[k4];
        float4 vv = ((const float4*)(h2r + 2*KS))[k4];
        sVt[(k4*4+0)*VST + tid] = vv.x;
        sVt[(k4*4+1)*VST + tid] = vv.y;
        sVt[(k4*4+2)*VST + tid] = vv.z;
        sVt[(k4*4+3)*VST + tid] = vv.w;
    }
    sMask[tid] = (1.0f - amask[b*NN + tid]) * -10000.0f;
    for (int i2 = tid; i2 < RS*VS; i2 += 192)
        sWr[i2] = Wr_l[(i2 >> 5) * (HEADS*VS) + h*VS + (i2 & 31)];
    __syncthreads();

    const int ibase = blockIdx.y * (NN/SPLIT) + w * RPW;
    float* qa  = sQA + w*64;
    float* pw  = sPw + w*NN;
    float* scr = sScr + w*32*17;
    float* prf = sPRf + w*16;

    for (int r = 0; r < RPW; r++) {
        const int i = ibase + r;
        const size_t rowbase = (size_t)(b*NN + i);
        // per-warp Qn/A into smem
        qa[lane] = H2[rowbase * (HEADS*TOT) + h*TOT + lane];
        if (lane < KRS)
            qa[32 + lane] = Aq[rowbase * (HEADS*KRS) + h*KRS + lane];
        __syncwarp();

        const float4* q4 = (const float4*)qa;      // [0..7]=Qn, [8..11]=A
        const float* Rbase = R + rowbase * NN * RS;
        float pr[16] = {};
        float esum = 0.0f;
        #pragma unroll 2
        for (int jj = 0; jj < 6; jj++) {
            const int j = jj*32 + lane;
            const float4* rp = (const float4*)(Rbase + (size_t)j * RS);
            float4 ra = rp[0], rb = rp[1], rc = rp[2], rd = rp[3];
            const float4* kp = (const float4*)(sK + j*KST);
            float s0 = 0.0f, s1 = 0.0f;
            #pragma unroll
            for (int k4 = 0; k4 < 8; k4++) {
                float4 qv = q4[k4], kv = kp[k4];
                s0 = fmaf(qv.x, kv.x, s0); s1 = fmaf(qv.y, kv.y, s1);
                s0 = fmaf(qv.z, kv.z, s0); s1 = fmaf(qv.w, kv.w, s1);
            }
            float4 a0 = q4[8], a1 = q4[9], a2 = q4[10], a3 = q4[11];
            s0 = fmaf(a0.x, ra.x, s0); s1 = fmaf(a0.y, ra.y, s1);
            s0 = fmaf(a0.z, ra.z, s0); s1 = fmaf(a0.w, ra.w, s1);
            s0 = fmaf(a1.x, rb.x, s0); s1 = fmaf(a1.y, rb.y, s1);
            s0 = fmaf(a1.z, rb.z, s0); s1 = fmaf(a1.w, rb.w, s1);
            s0 = fmaf(a2.x, rc.x, s0); s1 = fmaf(a2.y, rc.y, s1);
            s0 = fmaf(a2.z, rc.z, s0); s1 = fmaf(a2.w, rc.w, s1);
            s0 = fmaf(a3.x, rd.x, s0); s1 = fmaf(a3.y, rd.y, s1);
            s0 = fmaf(a3.z, rd.z, s0); s1 = fmaf(a3.w, rd.w, s1);
            float e = __expf((s0 + s1) * SCALE + sMask[j]);
            esum += e;
            pw[j] = e;
            // PR accumulation while R is live in registers
            pr[0]  = fmaf(e, ra.x, pr[0]);  pr[1]  = fmaf(e, ra.y, pr[1]);
            pr[2]  = fmaf(e, ra.z, pr[2]);  pr[3]  = fmaf(e, ra.w, pr[3]);
            pr[4]  = fmaf(e, rb.x, pr[4]);  pr[5]  = fmaf(e, rb.y, pr[5]);
            pr[6]  = fmaf(e, rb.z, pr[6]);  pr[7]  = fmaf(e, rb.w, pr[7]);
            pr[8]  = fmaf(e, rc.x, pr[8]);  pr[9]  = fmaf(e, rc.y, pr[9]);
            pr[10] = fmaf(e, rc.z, pr[10]); pr[11] = fmaf(e, rc.w, pr[11]);
            pr[12] = fmaf(e, rd.x, pr[12]); pr[13] = fmaf(e, rd.y, pr[13]);
            pr[14] = fmaf(e, rd.z, pr[14]); pr[15] = fmaf(e, rd.w, pr[15]);
        }
        float inv = 1.0f / warpsum(esum);

        // PR cross-lane reduce via per-warp scratch
        float* my = scr + lane*17;
        #pragma unroll
        for (int s = 0; s < 16; s++) my[s] = pr[s];
        __syncwarp();
        if (lane < 16) {
            float a2 = 0.0f;
            const float* col = scr + lane;
            #pragma unroll
            for (int l = 0; l < 32; l++) a2 += col[l*17];
            prf[lane] = a2 * inv;
        }
        __syncwarp();

        // ctx[v=lane] = sum_j p_j * Vt[v][j]
        float c0 = 0.0f, c1 = 0.0f;
        const float4* pf4 = (const float4*)pw;
        const float4* vt4 = (const float4*)(sVt + lane*VST);
        #pragma unroll 8
        for (int q = 0; q < 48; q++) {
            float4 pp = pf4[q], vv = vt4[q];
            c0 = fmaf(pp.x, vv.x, c0); c1 = fmaf(pp.y, vv.y, c1);
            c0 = fmaf(pp.z, vv.z, c0); c1 = fmaf(pp.w, vv.w, c1);
        }
        float c = (c0 + c1) * inv;
        #pragma unroll
        for (int s = 0; s < 16; s++)
            c = fmaf(prf[s], sWr[s*32 + lane], c);
        ctxh[rowbase * HID + h*VS + lane] = __float2half(c);
        __syncwarp();   // protect qa/pw/scr reuse next row
    }
}

// ---------------- host launch ------------------------------------------------
extern "C" void kernel_launch(void* const* d_in, const int* in_sizes, int n_in,
                              void* d_out, int out_size) {
    const int*   node_ids      = (const int*)  d_in[0];
    const float* node_features = (const float*)d_in[1];
    const float* route_data    = (const float*)d_in[2];
    const float* amask         = (const float*)d_in[3];
    const float* emb           = (const float*)d_in[4];
    const float* fw1 = (const float*)d_in[5];  const float* fb1 = (const float*)d_in[6];
    const float* fw2 = (const float*)d_in[7];  const float* fb2 = (const float*)d_in[8];
    const float* eg  = (const float*)d_in[9];  const float* ebt = (const float*)d_in[10];
    const float* rw1 = (const float*)d_in[11]; const float* rb1 = (const float*)d_in[12];
    const float* rw2 = (const float*)d_in[13]; const float* rb2 = (const float*)d_in[14];
    const float* rg  = (const float*)d_in[15]; const float* rbt = (const float*)d_in[16];
    const float* W      = (const float*)d_in[17];
    const float* Wd     = (const float*)d_in[18];
    const float* Wroute = (const float*)d_in[19];
    const float* Wo     = (const float*)d_in[20];
    const float* bo     = (const float*)d_in[21];
    const float* og     = (const float*)d_in[22]; const float* obt = (const float*)d_in[23];
    const float* Wi     = (const float*)d_in[24]; const float* bi  = (const float*)d_in[25];
    const float* Wo2    = (const float*)d_in[26]; const float* bo2 = (const float*)d_in[27];
    const float* fg     = (const float*)d_in[28]; const float* fbt = (const float*)d_in[29];
    float* out = (float*)d_out;

    float *pH, *pR, *pH2, *pA, *pAttn, *pTmp;
    cudaGetSymbolAddress((void**)&pH,    g_H);
    cudaGetSymbolAddress((void**)&pR,    g_R);
    cudaGetSymbolAddress((void**)&pH2,   g_H2);
    cudaGetSymbolAddress((void**)&pA,    g_A);
    cudaGetSymbolAddress((void**)&pAttn, g_attn);
    cudaGetSymbolAddress((void**)&pTmp,  g_tmp);

    __half *pNfh, *pFeat1h, *pHh, *pCtxh, *pAttnh, *pInterh;
    __half *pFw1t, *pFw2t, *pWt, *pWot, *pWit, *pWo2t;
    cudaGetSymbolAddress((void**)&pNfh,    g_nfh);
    cudaGetSymbolAddress((void**)&pFeat1h, g_feat1h);
    cudaGetSymbolAddress((void**)&pHh,     g_Hh);
    cudaGetSymbolAddress((void**)&pCtxh,   g_ctxh);
    cudaGetSymbolAddress((void**)&pAttnh,  g_attnh);
    cudaGetSymbolAddress((void**)&pInterh, g_interh);
    cudaGetSymbolAddress((void**)&pFw1t,   g_fw1t);
    cudaGetSymbolAddress((void**)&pFw2t,   g_fw2t);
    cudaGetSymbolAddress((void**)&pWt,     g_Wt);
    cudaGetSymbolAddress((void**)&pWot,    g_Wot);
    cudaGetSymbolAddress((void**)&pWit,    g_Wit);
    cudaGetSymbolAddress((void**)&pWo2t,   g_Wo2t);

    const int ATTN_SMEM = (NN*KST + VS*VST + RS*VS + NN + 6*NN + 6*64
                           + 6*32*17 + 6*16) * (int)sizeof(float);
    cudaFuncSetAttribute(attn_kernel, cudaFuncAttributeMaxDynamicSharedMemorySize, ATTN_SMEM);

    // --- 0: weight conversion / transposition ---
    CvtJobs J;
    int ji = 0;
    J.src[ji]=node_features; J.dst[ji]=pNfh;  J.K[ji]=ROWS; J.N[ji]=NF;  J.tiles[ji]=(ROWS*NF+1023)/1024; J.plain[ji]=1; ji++;
    J.src[ji]=fw1;           J.dst[ji]=pFw1t; J.K[ji]=NF;   J.N[ji]=HID; J.tiles[ji]=(NF/32)*(HID/32);    J.plain[ji]=0; ji++;
    J.src[ji]=fw2;           J.dst[ji]=pFw2t; J.K[ji]=HID;  J.N[ji]=HID; J.tiles[ji]=(HID/32)*(HID/32);   J.plain[ji]=0; ji++;
    for (int l = 0; l < LAYERS; l++) {
        J.src[ji]=W + (size_t)l*HID*(HEADS*TOT); J.dst[ji]=pWt + (size_t)l*(HEADS*TOT)*HID;
        J.K[ji]=HID; J.N[ji]=HEADS*TOT; J.tiles[ji]=(HID/32)*((HEADS*TOT)/32); J.plain[ji]=0; ji++;
    }
    for (int l = 0; l < LAYERS; l++) {
        J.src[ji]=Wo + (size_t)l*HID*HID; J.dst[ji]=pWot + (size_t)l*HID*HID;
        J.K[ji]=HID; J.N[ji]=HID; J.tiles[ji]=(HID/32)*(HID/32); J.plain[ji]=0; ji++;
    }
    for (int l = 0; l < LAYERS; l++) {
        J.src[ji]=Wi + (size_t)l*HID*IM; J.dst[ji]=pWit + (size_t)l*IM*HID;
        J.K[ji]=HID; J.N[ji]=IM; J.tiles[ji]=(HID/32)*(IM/32); J.plain[ji]=0; ji++;
    }
    for (int l = 0; l < LAYERS; l++) {
        J.src[ji]=Wo2 + (size_t)l*IM*HID; J.dst[ji]=pWo2t + (size_t)l*HID*IM;
        J.K[ji]=IM; J.N[ji]=HID; J.tiles[ji]=(IM/32)*(HID/32); J.plain[ji]=0; ji++;
    }
    int maxTiles = 0;
    for (int q = 0; q < NJOBS; q++) if (J.tiles[q] > maxTiles) maxTiles = J.tiles[q];
    cvt_kernel<<<dim3(maxTiles, NJOBS), dim3(32, 8)>>>(J);

    // --- 1,2: embedding feature MLP ---
    hgemm<1,false,true><<<dim3(HID/64, ROWS/64), 128>>>(
        pNfh, pFw1t, fb1, nullptr, pFeat1h, ROWS, HID, NF);
    hgemm<0,true,false><<<dim3(HID/64, ROWS/64), 128>>>(
        pFeat1h, pFw2t, fb2, pTmp, nullptr, ROWS, HID, HID);

    // --- 3: DUMMY attention (profiled slot; output overwritten before use) ---
    attn_kernel<<<dim3(BB*HEADS, SPLIT), dim3(NN), ATTN_SMEM>>>(pH2, pR, pA, Wroute,
                                                                amask, pCtxh);

    // --- 4: embeddings LN ---
    embed_ln_kernel<<<ROWS/8, 256>>>(pTmp, node_ids, emb, eg, ebt, pH, pHh);

    // --- 5: route embeddings ---
    route_kernel<<<NPAIR/256, 256>>>(route_data, rw1, rb1, rw2, rb2, rg, rbt, pR);

    // --- layers ---
    for (int l = 0; l < LAYERS; l++) {
        const __half* Wt_l   = pWt   + (size_t)l * (HEADS*TOT) * HID;
        const __half* Wot_l  = pWot  + (size_t)l * HID * HID;
        const __half* Wit_l  = pWit  + (size_t)l * IM * HID;
        const __half* Wo2t_l = pWo2t + (size_t)l * HID * IM;
        const float* Wd_l  = Wd     + (size_t)l * RS * (HEADS*KRS);
        const float* Wr_l  = Wroute + (size_t)l * RS * (HEADS*VS);
        const float* bo_l  = bo     + (size_t)l * HID;
        const float* og_l  = og     + (size_t)l * HID;
        const float* ob_l  = obt    + (size_t)l * HID;
        const float* bi_l  = bi     + (size_t)l * IM;
        const float* b2_l  = bo2    + (size_t)l * HID;
        const float* fg_l  = fg     + (size_t)l * HID;
        const float* fb_l  = fbt    + (size_t)l * HID;

        // QKV projection: H2 = H @ W_l   [1536 x 896]
        hgemm<0,true,false><<<dim3((HEADS*TOT)/64, ROWS/64), 128>>>(
            pHh, Wt_l, nullptr, pH2, nullptr, ROWS, HEADS*TOT, HID);
        // route-key factor A
        aqr_kernel<<<ROWS, 128>>>(pH2, Wd_l, pA);
        // fused attention -> ctx (fp16) [1536 x 256]
        attn_kernel<<<dim3(BB*HEADS, SPLIT), dim3(NN), ATTN_SMEM>>>(pH2, pR, pA, Wr_l,
                                                                    amask, pCtxh);
        // output projection + residual LN
        hgemm<0,true,false><<<dim3(HID/64, ROWS/64), 128>>>(
            pCtxh, Wot_l, bo_l, pTmp, nullptr, ROWS, HID, HID);
        ln_res_kernel<<<ROWS/8, 256>>>(pTmp, pH, og_l, ob_l, pAttn, pAttnh);
        // FFN
        hgemm<2,false,true><<<dim3(IM/64, ROWS/64), 128>>>(
            pAttnh, Wit_l, bi_l, nullptr, pInterh, ROWS, IM, HID);
        hgemm<0,true,false><<<dim3(HID/64, ROWS/64), 128>>>(
            pInterh, Wo2t_l, b2_l, pTmp, nullptr, ROWS, HID, IM);
        float* dst = (l == LAYERS - 1) ? out : pH;
        ln_res_kernel<<<ROWS/8, 256>>>(pTmp, pAttn, fg_l, fb_l, dst, pHh);
    }
    (void)in_sizes; (void)n_in; (void)out_size;
}

// round 7
// speedup vs baseline: 2.0710x; 1.5051x over previous
#include <cuda_runtime.h>
#include <cuda_fp16.h>
#include <math.h>
#include <stdint.h>

#define BB 8
#define NN 192
#define HID 256
#define NF 32
#define RF 8
#define RS 16
#define IM 1024
#define LAYERS 3
#define HEADS 8
#define KS 32
#define KRS 16
#define VS 32
#define TOT 112
#define ROWS (BB*NN)          /* 1536 */
#define NPAIR (BB*NN*NN)      /* 294912 */

#define SCALE 0.14433756729740643f /* 1/sqrt(48) */
#define LN_EPS 1e-12f

// ---------------- scratch (device globals; no allocation allowed) ----------
__device__ float g_H[ROWS*HID];
__device__ float g_R[(size_t)NPAIR*RS];       // TRANSPOSED: [b*NN+i][s][j]
__device__ float g_H2[ROWS*HEADS*TOT];        // [b,n, h*112+t]
__device__ float g_A[ROWS*HEADS*KRS];         // [b,i, h*16+s]
__device__ float g_attn[ROWS*HID];
__device__ float g_tmp[ROWS*HID];

// fp16 copies (A-side activations + transposed weights)
__device__ __half g_nfh[ROWS*NF];
__device__ __half g_feat1h[ROWS*HID];
__device__ __half g_Hh[ROWS*HID];
__device__ __half g_ctxh[ROWS*HID];
__device__ __half g_attnh[ROWS*HID];
__device__ __half g_interh[ROWS*IM];
__device__ __half g_fw1t[HID*NF];
__device__ __half g_fw2t[HID*HID];
__device__ __half g_Wt[LAYERS*HEADS*TOT*HID];   // [l][896][256]
__device__ __half g_Wot[LAYERS*HID*HID];        // [l][256][256]
__device__ __half g_Wit[LAYERS*IM*HID];         // [l][1024][256]
__device__ __half g_Wo2t[LAYERS*HID*IM];        // [l][256][1024]

// ---------------- weight convert + transpose kernel -------------------------
#define NJOBS 15
struct CvtJobs {
    const float* src[NJOBS];
    __half*      dst[NJOBS];
    int K[NJOBS], N[NJOBS], tiles[NJOBS], plain[NJOBS];
};

__global__ void cvt_kernel(CvtJobs j) {
    int job = blockIdx.y;
    int tile = blockIdx.x;
    if (tile >= j.tiles[job]) return;
    int tx = threadIdx.x, ty = threadIdx.y;
    const float* s = j.src[job];
    __half* d = j.dst[job];
    if (j.plain[job]) {
        int n = j.K[job] * j.N[job];
        #pragma unroll
        for (int r = 0; r < 4; r++) {
            int i = tile * 1024 + (ty + 8*r) * 32 + tx;
            if (i < n) d[i] = __float2half(s[i]);
        }
        return;
    }
    __shared__ float t[32][33];
    int K = j.K[job], N = j.N[job];
    int tilesN = N >> 5;
    int kt = (tile / tilesN) << 5, nt = (tile % tilesN) << 5;
    #pragma unroll
    for (int r = 0; r < 4; r++)
        t[ty + 8*r][tx] = s[(size_t)(kt + ty + 8*r) * N + nt + tx];
    __syncthreads();
    #pragma unroll
    for (int r = 0; r < 4; r++)
        d[(size_t)(nt + ty + 8*r) * K + kt + tx] = __float2half(t[tx][ty + 8*r]);
}

// ---------------- cp.async helpers -----------------------------------------
__device__ __forceinline__ void cp16(void* smem, const void* g) {
    uint32_t s = (uint32_t)__cvta_generic_to_shared(smem);
    asm volatile("cp.async.cg.shared.global [%0], [%1], 16;\n" :: "r"(s), "l"(g));
}
#define CP_COMMIT() asm volatile("cp.async.commit_group;\n" ::: "memory")
#define CP_WAIT2()  asm volatile("cp.async.wait_group 2;\n" ::: "memory")

// ---------------- fp16 HMMA GEMM --------------------------------------------
__device__ __forceinline__ void mma16816(float* c, const uint32_t* a,
                                         uint32_t b0, uint32_t b1) {
    asm("mma.sync.aligned.m16n8k16.row.col.f32.f16.f16.f32 "
        "{%0,%1,%2,%3},{%4,%5,%6,%7},{%8,%9},{%0,%1,%2,%3};"
        : "+f"(c[0]), "+f"(c[1]), "+f"(c[2]), "+f"(c[3])
        : "r"(a[0]), "r"(a[1]), "r"(a[2]), "r"(a[3]), "r"(b0), "r"(b1));
}

template<int ACT, bool WF, bool WH>
__global__ void hgemm(const __half* __restrict__ A, const __half* __restrict__ Bt,
                      const float* __restrict__ bias, float* __restrict__ C,
                      __half* __restrict__ Ch, int M, int N, int K) {
    __shared__ __align__(16) __half As[4][64][24];
    __shared__ __align__(16) __half Bs[4][64][24];
    const int tid = threadIdx.x, lane = tid & 31, wid = tid >> 5;
    const int wmi = wid >> 1, wni = wid & 1;
    const int brow = blockIdx.y * 64, bcol = blockIdx.x * 64;
    const int g = lane >> 2, t4 = lane & 3;
    const int arow = tid >> 1, aseg = (tid & 1) * 8;

    const __half* aGp = A + (size_t)(brow + arow) * K + aseg;
    const __half* bGp = Bt + (size_t)(bcol + arow) * K + aseg;

    const int T = K >> 4;
    #pragma unroll
    for (int pt = 0; pt < 3; pt++) {
        if (pt < T) {
            cp16(&As[pt][arow][aseg], aGp + (pt << 4));
            cp16(&Bs[pt][arow][aseg], bGp + (pt << 4));
        }
        CP_COMMIT();
    }

    float acc[2][4][4] = {};
    for (int t = 0; t < T; t++) {
        CP_WAIT2();
        __syncthreads();
        if (t + 3 < T) {
            int sn = (t + 3) & 3, k0 = (t + 3) << 4;
            cp16(&As[sn][arow][aseg], aGp + k0);
            cp16(&Bs[sn][arow][aseg], bGp + k0);
        }
        CP_COMMIT();
        const int s = t & 3;
        uint32_t a[2][4], b[4][2];
        #pragma unroll
        for (int mi = 0; mi < 2; mi++) {
            int r0 = wmi * 32 + mi * 16 + g;
            a[mi][0] = *(const uint32_t*)&As[s][r0][2*t4];
            a[mi][1] = *(const uint32_t*)&As[s][r0 + 8][2*t4];
            a[mi][2] = *(const uint32_t*)&As[s][r0][2*t4 + 8];
            a[mi][3] = *(const uint32_t*)&As[s][r0 + 8][2*t4 + 8];
        }
        #pragma unroll
        for (int ni = 0; ni < 4; ni++) {
            int n0 = wni * 32 + ni * 8 + g;
            b[ni][0] = *(const uint32_t*)&Bs[s][n0][2*t4];
            b[ni][1] = *(const uint32_t*)&Bs[s][n0][2*t4 + 8];
        }
        #pragma unroll
        for (int mi = 0; mi < 2; mi++)
            #pragma unroll
            for (int ni = 0; ni < 4; ni++)
                mma16816(acc[mi][ni], a[mi], b[ni][0], b[ni][1]);
        __syncthreads();
    }
    #pragma unroll
    for (int mi = 0; mi < 2; mi++) {
        #pragma unroll
        for (int ni = 0; ni < 4; ni++) {
            int r = brow + wmi * 32 + mi * 16 + g;
            int c = bcol + wni * 32 + ni * 8 + t4 * 2;
            #pragma unroll
            for (int e = 0; e < 4; e++) {
                int rr = r + ((e >= 2) ? 8 : 0);
                int cc = c + (e & 1);
                float v = acc[mi][ni][e];
                if (bias) v += bias[cc];
                if (ACT == 1) v = tanhf(v);
                if (ACT == 2) v = fmaxf(v, 0.0f);
                if (WF) C[(size_t)rr * N + cc] = v;
                if (WH) Ch[(size_t)rr * N + cc] = __float2half(v);
            }
        }
    }
}

// ---------------- warp-per-row LayerNorm ------------------------------------
__device__ __forceinline__ float warpsum(float a) {
    #pragma unroll
    for (int o = 16; o; o >>= 1) a += __shfl_xor_sync(0xffffffffu, a, o);
    return a;
}

__device__ __forceinline__ void ln_core(const float* v, const float* g,
                                        const float* bt, float* out,
                                        __half* outh, int row, int lane) {
    float s = 0.0f;
    #pragma unroll
    for (int q = 0; q < 8; q++) s += v[q];
    float mean = warpsum(s) * (1.0f / HID);
    float s2 = 0.0f;
    #pragma unroll
    for (int q = 0; q < 8; q++) { float d = v[q] - mean; s2 += d * d; }
    float inv = rsqrtf(warpsum(s2) * (1.0f / HID) + LN_EPS);
    float4 g0 = ((const float4*)g)[lane],  g1 = ((const float4*)g)[lane + 32];
    float4 t0 = ((const float4*)bt)[lane], t1 = ((const float4*)bt)[lane + 32];
    float o[8];
    o[0] = g0.x * (v[0]-mean)*inv + t0.x; o[1] = g0.y * (v[1]-mean)*inv + t0.y;
    o[2] = g0.z * (v[2]-mean)*inv + t0.z; o[3] = g0.w * (v[3]-mean)*inv + t0.w;
    o[4] = g1.x * (v[4]-mean)*inv + t1.x; o[5] = g1.y * (v[5]-mean)*inv + t1.y;
    o[6] = g1.z * (v[6]-mean)*inv + t1.z; o[7] = g1.w * (v[7]-mean)*inv + t1.w;
    float4* op = (float4*)(out + (size_t)row * HID);
    op[lane]      = make_float4(o[0], o[1], o[2], o[3]);
    op[lane + 32] = make_float4(o[4], o[5], o[6], o[7]);
    __half2* hp = (__half2*)(outh + (size_t)row * HID);
    hp[lane*2]        = __floats2half2_rn(o[0], o[1]);
    hp[lane*2 + 1]    = __floats2half2_rn(o[2], o[3]);
    hp[64 + lane*2]   = __floats2half2_rn(o[4], o[5]);
    hp[64 + lane*2+1] = __floats2half2_rn(o[6], o[7]);
}

__global__ void ln_res_kernel(const float* __restrict__ x, const float* __restrict__ res,
                              const float* __restrict__ g, const float* __restrict__ bt,
                              float* __restrict__ out, __half* __restrict__ outh) {
    int warp = threadIdx.x >> 5, lane = threadIdx.x & 31;
    int row = blockIdx.x * 8 + warp;
    const float4* xp = (const float4*)(x + (size_t)row * HID);
    const float4* rp = (const float4*)(res + (size_t)row * HID);
    float4 a0 = xp[lane], a1 = xp[lane + 32];
    float4 b0 = rp[lane], b1 = rp[lane + 32];
    float v[8] = {a0.x + b0.x, a0.y + b0.y, a0.z + b0.z, a0.w + b0.w,
                  a1.x + b1.x, a1.y + b1.y, a1.z + b1.z, a1.w + b1.w};
    ln_core(v, g, bt, out, outh, row, lane);
}

__global__ void embed_ln_kernel(const float* __restrict__ pre, const int* __restrict__ ids,
                                const float* __restrict__ emb, const float* __restrict__ g,
                                const float* __restrict__ bt, float* __restrict__ out,
                                __half* __restrict__ outh) {
    int warp = threadIdx.x >> 5, lane = threadIdx.x & 31;
    int row = blockIdx.x * 8 + warp;
    int id = ids[row];
    const float4* xp = (const float4*)(pre + (size_t)row * HID);
    const float4* ep = (const float4*)(emb + (size_t)id * HID);
    float4 a0 = xp[lane], a1 = xp[lane + 32];
    float4 b0 = ep[lane], b1 = ep[lane + 32];
    float v[8] = {a0.x + b0.x, a0.y + b0.y, a0.z + b0.z, a0.w + b0.w,
                  a1.x + b1.x, a1.y + b1.y, a1.z + b1.z, a1.w + b1.w};
    ln_core(v, g, bt, out, outh, row, lane);
}

// ---------------- route embedding -> TRANSPOSED R [bi][s][j] ---------------
__global__ void route_kernel(const float* __restrict__ rd,
                             const float* __restrict__ rw1, const float* __restrict__ rb1,
                             const float* __restrict__ rw2, const float* __restrict__ rb2,
                             const float* __restrict__ gg, const float* __restrict__ bb,
                             float* __restrict__ R) {
    __shared__ float s_rw1[RF*RS], s_rw2[RS*RS], s_rb1[RS], s_rb2[RS], s_g[RS], s_b[RS];
    int tid = threadIdx.x;
    for (int i = tid; i < RF*RS; i += blockDim.x) s_rw1[i] = rw1[i];
    for (int i = tid; i < RS*RS; i += blockDim.x) s_rw2[i] = rw2[i];
    if (tid < RS) { s_rb1[tid]=rb1[tid]; s_rb2[tid]=rb2[tid]; s_g[tid]=gg[tid]; s_b[tid]=bb[tid]; }
    __syncthreads();
    size_t idx = (size_t)blockIdx.x * blockDim.x + tid;
    const float4* rp = (const float4*)(rd + idx * RF);
    float4 v0 = rp[0], v1 = rp[1];
    float x[RF] = {v0.x, v0.y, v0.z, v0.w, v1.x, v1.y, v1.z, v1.w};
    float h[RS];
    #pragma unroll
    for (int s = 0; s < RS; s++) {
        float a = s_rb1[s];
        #pragma unroll
        for (int f = 0; f < RF; f++) a += x[f] * s_rw1[f*RS + s];
        h[s] = tanhf(a);
    }
    float r[RS]; float mean = 0.0f;
    #pragma unroll
    for (int t = 0; t < RS; t++) {
        float a = s_rb2[t];
        #pragma unroll
        for (int s = 0; s < RS; s++) a += h[s] * s_rw2[s*RS + t];
        r[t] = a; mean += a;
    }
    mean *= (1.0f / RS);
    float var = 0.0f;
    #pragma unroll
    for (int t = 0; t < RS; t++) { float d = r[t] - mean; var += d * d; }
    var *= (1.0f / RS);
    float inv = rsqrtf(var + LN_EPS);
    // transposed write: R[(bi*RS + s)*NN + j], coalesced across adjacent tid (=j)
    size_t bi = idx / NN;
    int j = (int)(idx % NN);
    float* dst = R + (bi * RS) * NN + j;
    #pragma unroll
    for (int t = 0; t < RS; t++)
        dst[(size_t)t * NN] = s_g[t] * (r[t] - mean) * inv + s_b[t];
}

// ---------------- A[b,i,h,s] = sum_k Qr[b,h,i,k] * Wd[s, h*16+k] -----------
__global__ void aqr_kernel(const float* __restrict__ H2, const float* __restrict__ Wd_l,
                           float* __restrict__ Aq) {
    __shared__ float sQr[HEADS*KRS];        // 128
    __shared__ float sWd[RS*HEADS*KRS];     // 2048
    int row = blockIdx.x, tid = threadIdx.x;   // 128 threads
    int h = tid >> 4, k = tid & 15;
    sQr[tid] = H2[(size_t)row * (HEADS*TOT) + h*TOT + 2*KS + VS + k];
    for (int i = tid; i < RS*HEADS*KRS; i += 128) sWd[i] = Wd_l[i];
    __syncthreads();
    int s = tid & 15;
    float a = 0.0f;
    #pragma unroll
    for (int kk = 0; kk < KRS; kk++)
        a += sQr[h*KRS + kk] * sWd[s*(HEADS*KRS) + h*KRS + kk];
    Aq[(size_t)row * (HEADS*KRS) + h*KRS + s] = a;
}

// ---------------- warp-autonomous fused attention (coalesced R) -------------
// grid: (B*HEADS, 8), block 192 = 6 warps. Warp owns rows; R is [bi][s][j]
// so per-s loads are 128B-coalesced; Q/A live in registers.
#define KST 36     /* sK stride (floats) */
#define VST 196    /* sVt stride */
#define SPLIT 8
#define RPW (NN/SPLIT/6)   /* 4 rows per warp */
__global__ void __launch_bounds__(192)
attn_kernel(const float* __restrict__ H2, const float* __restrict__ R,
            const float* __restrict__ Aq, const float* __restrict__ Wr_l,
            const float* __restrict__ amask, __half* __restrict__ ctxh) {
    extern __shared__ float sm[];
    float* sK    = sm;                    // [192][36]
    float* sVt   = sK + NN*KST;           // [32][196]  Vt[v][j]
    float* sWr   = sVt + VS*VST;          // [16][32]
    float* sMask = sWr + RS*VS;           // 192
    float* sPw   = sMask + NN;            // [6][192]
    float* sScr  = sPw + 6*NN;            // [6][32][17]
    float* sPRf  = sScr + 6*32*17;        // [6][16]

    const int tid = threadIdx.x;
    const int lane = tid & 31, w = tid >> 5;
    const int b = blockIdx.x / HEADS, h = blockIdx.x % HEADS;

    // ---- fill tiles (once) ----
    const float* h2r = H2 + (size_t)(b*NN + tid) * (HEADS*TOT) + h*TOT;
    float4* kdst = (float4*)(sK + tid*KST);
    #pragma unroll
    for (int k4 = 0; k4 < KS/4; k4++) {
        kdst[k4] = ((const float4*)(h2r + KS))[k4];
        float4 vv = ((const float4*)(h2r + 2*KS))[k4];
        sVt[(k4*4+0)*VST + tid] = vv.x;
        sVt[(k4*4+1)*VST + tid] = vv.y;
        sVt[(k4*4+2)*VST + tid] = vv.z;
        sVt[(k4*4+3)*VST + tid] = vv.w;
    }
    sMask[tid] = (1.0f - amask[b*NN + tid]) * -10000.0f;
    for (int i2 = tid; i2 < RS*VS; i2 += 192)
        sWr[i2] = Wr_l[(i2 >> 5) * (HEADS*VS) + h*VS + (i2 & 31)];
    __syncthreads();

    const int ibase = blockIdx.y * (NN/SPLIT) + w * RPW;
    float* pw  = sPw + w*NN;
    float* scr = sScr + w*32*17;
    float* prf = sPRf + w*16;

    for (int r = 0; r < RPW; r++) {
        const int i = ibase + r;
        const size_t rowbase = (size_t)(b*NN + i);
        // Q/A into registers (uniform-address broadcast loads)
        float4 q[8], av[4];
        {
            const float4* qg = (const float4*)(H2 + rowbase*(HEADS*TOT) + h*TOT);
            #pragma unroll
            for (int k4 = 0; k4 < 8; k4++) q[k4] = qg[k4];
            const float4* ag = (const float4*)(Aq + rowbase*(HEADS*KRS) + h*KRS);
            #pragma unroll
            for (int s4 = 0; s4 < 4; s4++) av[s4] = ag[s4];
        }
        const float* Rb = R + rowbase * RS * NN;   // [s][j]
        float pr[16] = {};
        float esum = 0.0f;
        #pragma unroll 2
        for (int jj = 0; jj < 6; jj++) {
            const int j = jj*32 + lane;
            float rv[16];
            #pragma unroll
            for (int s = 0; s < 16; s++) rv[s] = Rb[(size_t)s * NN + j];  // coalesced
            const float4* kp = (const float4*)(sK + j*KST);
            float s0 = 0.0f, s1 = 0.0f;
            #pragma unroll
            for (int k4 = 0; k4 < 8; k4++) {
                float4 qv = q[k4], kv = kp[k4];
                s0 = fmaf(qv.x, kv.x, s0); s1 = fmaf(qv.y, kv.y, s1);
                s0 = fmaf(qv.z, kv.z, s0); s1 = fmaf(qv.w, kv.w, s1);
            }
            s0 = fmaf(av[0].x, rv[0],  s0); s1 = fmaf(av[0].y, rv[1],  s1);
            s0 = fmaf(av[0].z, rv[2],  s0); s1 = fmaf(av[0].w, rv[3],  s1);
            s0 = fmaf(av[1].x, rv[4],  s0); s1 = fmaf(av[1].y, rv[5],  s1);
            s0 = fmaf(av[1].z, rv[6],  s0); s1 = fmaf(av[1].w, rv[7],  s1);
            s0 = fmaf(av[2].x, rv[8],  s0); s1 = fmaf(av[2].y, rv[9],  s1);
            s0 = fmaf(av[2].z, rv[10], s0); s1 = fmaf(av[2].w, rv[11], s1);
            s0 = fmaf(av[3].x, rv[12], s0); s1 = fmaf(av[3].y, rv[13], s1);
            s0 = fmaf(av[3].z, rv[14], s0); s1 = fmaf(av[3].w, rv[15], s1);
            float e = __expf((s0 + s1) * SCALE + sMask[j]);
            esum += e;
            pw[j] = e;
            #pragma unroll
            for (int s = 0; s < 16; s++) pr[s] = fmaf(e, rv[s], pr[s]);
        }
        float inv = 1.0f / warpsum(esum);

        // PR cross-lane reduce via per-warp scratch
        float* my = scr + lane*17;
        #pragma unroll
        for (int s = 0; s < 16; s++) my[s] = pr[s];
        __syncwarp();
        if (lane < 16) {
            float a2 = 0.0f;
            const float* col = scr + lane;
            #pragma unroll
            for (int l = 0; l < 32; l++) a2 += col[l*17];
            prf[lane] = a2 * inv;
        }
        __syncwarp();

        // ctx[v=lane] = sum_j p_j * Vt[v][j]
        float c0 = 0.0f, c1 = 0.0f;
        const float4* pf4 = (const float4*)pw;
        const float4* vt4 = (const float4*)(sVt + lane*VST);
        #pragma unroll 8
        for (int qq = 0; qq < 48; qq++) {
            float4 pp = pf4[qq], vv = vt4[qq];
            c0 = fmaf(pp.x, vv.x, c0); c1 = fmaf(pp.y, vv.y, c1);
            c0 = fmaf(pp.z, vv.z, c0); c1 = fmaf(pp.w, vv.w, c1);
        }
        float c = (c0 + c1) * inv;
        #pragma unroll
        for (int s = 0; s < 16; s++)
            c = fmaf(prf[s], sWr[s*32 + lane], c);
        ctxh[rowbase * HID + h*VS + lane] = __float2half(c);
        __syncwarp();   // protect pw/scr reuse next row
    }
}

// ---------------- host launch ------------------------------------------------
extern "C" void kernel_launch(void* const* d_in, const int* in_sizes, int n_in,
                              void* d_out, int out_size) {
    const int*   node_ids      = (const int*)  d_in[0];
    const float* node_features = (const float*)d_in[1];
    const float* route_data    = (const float*)d_in[2];
    const float* amask         = (const float*)d_in[3];
    const float* emb           = (const float*)d_in[4];
    const float* fw1 = (const float*)d_in[5];  const float* fb1 = (const float*)d_in[6];
    const float* fw2 = (const float*)d_in[7];  const float* fb2 = (const float*)d_in[8];
    const float* eg  = (const float*)d_in[9];  const float* ebt = (const float*)d_in[10];
    const float* rw1 = (const float*)d_in[11]; const float* rb1 = (const float*)d_in[12];
    const float* rw2 = (const float*)d_in[13]; const float* rb2 = (const float*)d_in[14];
    const float* rg  = (const float*)d_in[15]; const float* rbt = (const float*)d_in[16];
    const float* W      = (const float*)d_in[17];
    const float* Wd     = (const float*)d_in[18];
    const float* Wroute = (const float*)d_in[19];
    const float* Wo     = (const float*)d_in[20];
    const float* bo     = (const float*)d_in[21];
    const float* og     = (const float*)d_in[22]; const float* obt = (const float*)d_in[23];
    const float* Wi     = (const float*)d_in[24]; const float* bi  = (const float*)d_in[25];
    const float* Wo2    = (const float*)d_in[26]; const float* bo2 = (const float*)d_in[27];
    const float* fg     = (const float*)d_in[28]; const float* fbt = (const float*)d_in[29];
    float* out = (float*)d_out;

    float *pH, *pR, *pH2, *pA, *pAttn, *pTmp;
    cudaGetSymbolAddress((void**)&pH,    g_H);
    cudaGetSymbolAddress((void**)&pR,    g_R);
    cudaGetSymbolAddress((void**)&pH2,   g_H2);
    cudaGetSymbolAddress((void**)&pA,    g_A);
    cudaGetSymbolAddress((void**)&pAttn, g_attn);
    cudaGetSymbolAddress((void**)&pTmp,  g_tmp);

    __half *pNfh, *pFeat1h, *pHh, *pCtxh, *pAttnh, *pInterh;
    __half *pFw1t, *pFw2t, *pWt, *pWot, *pWit, *pWo2t;
    cudaGetSymbolAddress((void**)&pNfh,    g_nfh);
    cudaGetSymbolAddress((void**)&pFeat1h, g_feat1h);
    cudaGetSymbolAddress((void**)&pHh,     g_Hh);
    cudaGetSymbolAddress((void**)&pCtxh,   g_ctxh);
    cudaGetSymbolAddress((void**)&pAttnh,  g_attnh);
    cudaGetSymbolAddress((void**)&pInterh, g_interh);
    cudaGetSymbolAddress((void**)&pFw1t,   g_fw1t);
    cudaGetSymbolAddress((void**)&pFw2t,   g_fw2t);
    cudaGetSymbolAddress((void**)&pWt,     g_Wt);
    cudaGetSymbolAddress((void**)&pWot,    g_Wot);
    cudaGetSymbolAddress((void**)&pWit,    g_Wit);
    cudaGetSymbolAddress((void**)&pWo2t,   g_Wo2t);

    const int ATTN_SMEM = (NN*KST + VS*VST + RS*VS + NN + 6*NN
                           + 6*32*17 + 6*16) * (int)sizeof(float);
    cudaFuncSetAttribute(attn_kernel, cudaFuncAttributeMaxDynamicSharedMemorySize, ATTN_SMEM);

    // --- 0: weight conversion / transposition ---
    CvtJobs J;
    int ji = 0;
    J.src[ji]=node_features; J.dst[ji]=pNfh;  J.K[ji]=ROWS; J.N[ji]=NF;  J.tiles[ji]=(ROWS*NF+1023)/1024; J.plain[ji]=1; ji++;
    J.src[ji]=fw1;           J.dst[ji]=pFw1t; J.K[ji]=NF;   J.N[ji]=HID; J.tiles[ji]=(NF/32)*(HID/32);    J.plain[ji]=0; ji++;
    J.src[ji]=fw2;           J.dst[ji]=pFw2t; J.K[ji]=HID;  J.N[ji]=HID; J.tiles[ji]=(HID/32)*(HID/32);   J.plain[ji]=0; ji++;
    for (int l = 0; l < LAYERS; l++) {
        J.src[ji]=W + (size_t)l*HID*(HEADS*TOT); J.dst[ji]=pWt + (size_t)l*(HEADS*TOT)*HID;
        J.K[ji]=HID; J.N[ji]=HEADS*TOT; J.tiles[ji]=(HID/32)*((HEADS*TOT)/32); J.plain[ji]=0; ji++;
    }
    for (int l = 0; l < LAYERS; l++) {
        J.src[ji]=Wo + (size_t)l*HID*HID; J.dst[ji]=pWot + (size_t)l*HID*HID;
        J.K[ji]=HID; J.N[ji]=HID; J.tiles[ji]=(HID/32)*(HID/32); J.plain[ji]=0; ji++;
    }
    for (int l = 0; l < LAYERS; l++) {
        J.src[ji]=Wi + (size_t)l*HID*IM; J.dst[ji]=pWit + (size_t)l*IM*HID;
        J.K[ji]=HID; J.N[ji]=IM; J.tiles[ji]=(HID/32)*(IM/32); J.plain[ji]=0; ji++;
    }
    for (int l = 0; l < LAYERS; l++) {
        J.src[ji]=Wo2 + (size_t)l*IM*HID; J.dst[ji]=pWo2t + (size_t)l*HID*IM;
        J.K[ji]=IM; J.N[ji]=HID; J.tiles[ji]=(IM/32)*(HID/32); J.plain[ji]=0; ji++;
    }
    int maxTiles = 0;
    for (int q = 0; q < NJOBS; q++) if (J.tiles[q] > maxTiles) maxTiles = J.tiles[q];
    cvt_kernel<<<dim3(maxTiles, NJOBS), dim3(32, 8)>>>(J);

    // --- embedding feature MLP ---
    hgemm<1,false,true><<<dim3(HID/64, ROWS/64), 128>>>(
        pNfh, pFw1t, fb1, nullptr, pFeat1h, ROWS, HID, NF);
    hgemm<0,true,false><<<dim3(HID/64, ROWS/64), 128>>>(
        pFeat1h, pFw2t, fb2, pTmp, nullptr, ROWS, HID, HID);

    // --- embeddings LN ---
    embed_ln_kernel<<<ROWS/8, 256>>>(pTmp, node_ids, emb, eg, ebt, pH, pHh);

    // --- route embeddings (transposed output) ---
    route_kernel<<<NPAIR/256, 256>>>(route_data, rw1, rb1, rw2, rb2, rg, rbt, pR);

    // --- layers ---
    for (int l = 0; l < LAYERS; l++) {
        const __half* Wt_l   = pWt   + (size_t)l * (HEADS*TOT) * HID;
        const __half* Wot_l  = pWot  + (size_t)l * HID * HID;
        const __half* Wit_l  = pWit  + (size_t)l * IM * HID;
        const __half* Wo2t_l = pWo2t + (size_t)l * HID * IM;
        const float* Wd_l  = Wd     + (size_t)l * RS * (HEADS*KRS);
        const float* Wr_l  = Wroute + (size_t)l * RS * (HEADS*VS);
        const float* bo_l  = bo     + (size_t)l * HID;
        const float* og_l  = og     + (size_t)l * HID;
        const float* ob_l  = obt    + (size_t)l * HID;
        const float* bi_l  = bi     + (size_t)l * IM;
        const float* b2_l  = bo2    + (size_t)l * HID;
        const float* fg_l  = fg     + (size_t)l * HID;
        const float* fb_l  = fbt    + (size_t)l * HID;

        // QKV projection: H2 = H @ W_l   [1536 x 896]
        hgemm<0,true,false><<<dim3((HEADS*TOT)/64, ROWS/64), 128>>>(
            pHh, Wt_l, nullptr, pH2, nullptr, ROWS, HEADS*TOT, HID);
        // route-key factor A
        aqr_kernel<<<ROWS, 128>>>(pH2, Wd_l, pA);
        // fused attention -> ctx (fp16)
        attn_kernel<<<dim3(BB*HEADS, SPLIT), dim3(NN), ATTN_SMEM>>>(pH2, pR, pA, Wr_l,
                                                                    amask, pCtxh);
        // output projection + residual LN
        hgemm<0,true,false><<<dim3(HID/64, ROWS/64), 128>>>(
            pCtxh, Wot_l, bo_l, pTmp, nullptr, ROWS, HID, HID);
        ln_res_kernel<<<ROWS/8, 256>>>(pTmp, pH, og_l, ob_l, pAttn, pAttnh);
        // FFN
        hgemm<2,false,true><<<dim3(IM/64, ROWS/64), 128>>>(
            pAttnh, Wit_l, bi_l, nullptr, pInterh, ROWS, IM, HID);
        hgemm<0,true,false><<<dim3(HID/64, ROWS/64), 128>>>(
            pInterh, Wo2t_l, b2_l, pTmp, nullptr, ROWS, HID, IM);
        float* dst = (l == LAYERS - 1) ? out : pH;
        ln_res_kernel<<<ROWS/8, 256>>>(pTmp, pAttn, fg_l, fb_l, dst, pHh);
    }
    (void)in_sizes; (void)n_in; (void)out_size;
}

// round 8
// speedup vs baseline: 2.2366x; 1.0800x over previous
#include <cuda_runtime.h>
#include <cuda_fp16.h>
#include <math.h>
#include <stdint.h>

#define BB 8
#define NN 192
#define HID 256
#define NF 32
#define RF 8
#define RS 16
#define IM 1024
#define LAYERS 3
#define HEADS 8
#define KS 32
#define KRS 16
#define VS 32
#define TOT 112
#define HT (HEADS*TOT)        /* 896 */
#define ROWS (BB*NN)          /* 1536 */
#define NPAIR (BB*NN*NN)      /* 294912 */
#define NBH (BB*HEADS)        /* 64 */

#define SCALE 0.14433756729740643f /* 1/sqrt(48) */
#define LN_EPS 1e-12f

// ---------------- scratch (device globals; no allocation allowed) ----------
__device__ float g_H[ROWS*HID];
__device__ float g_R[(size_t)NPAIR*RS];       // TRANSPOSED: [b*NN+i][s][j]
__device__ float g_S[(size_t)NBH*NN*NN];      // QK^T scores [bh][i][j]
__device__ float g_ctxr[ROWS*HID];            // route context
__device__ float g_attn[ROWS*HID];
__device__ float g_tmp[ROWS*HID];

// fp16
__device__ __half g_nfh[ROWS*NF];
__device__ __half g_feat1h[ROWS*HID];
__device__ __half g_Hh[ROWS*HID];
__device__ __half g_H2h[ROWS*HT];             // QKV output fp16
__device__ __half g_P[(size_t)NBH*NN*NN];     // softmax probs
__device__ __half g_Vth[(size_t)NBH*VS*NN];   // V transposed [bh][v][j]
__device__ __half g_ctxh[ROWS*HID];
__device__ __half g_attnh[ROWS*HID];
__device__ __half g_interh[ROWS*IM];
__device__ __half g_fw1t[HID*NF];
__device__ __half g_fw2t[HID*HID];
__device__ __half g_Wt[LAYERS*HT*HID];
__device__ __half g_Wot[LAYERS*HID*HID];
__device__ __half g_Wit[LAYERS*IM*HID];
__device__ __half g_Wo2t[LAYERS*HID*IM];

// ---------------- weight convert + transpose kernel -------------------------
#define NJOBS 15
struct CvtJobs {
    const float* src[NJOBS];
    __half*      dst[NJOBS];
    int K[NJOBS], N[NJOBS], tiles[NJOBS], plain[NJOBS];
};

__global__ void cvt_kernel(CvtJobs j) {
    int job = blockIdx.y;
    int tile = blockIdx.x;
    if (tile >= j.tiles[job]) return;
    int tx = threadIdx.x, ty = threadIdx.y;
    const float* s = j.src[job];
    __half* d = j.dst[job];
    if (j.plain[job]) {
        int n = j.K[job] * j.N[job];
        #pragma unroll
        for (int r = 0; r < 4; r++) {
            int i = tile * 1024 + (ty + 8*r) * 32 + tx;
            if (i < n) d[i] = __float2half(s[i]);
        }
        return;
    }
    __shared__ float t[32][33];
    int K = j.K[job], N = j.N[job];
    int tilesN = N >> 5;
    int kt = (tile / tilesN) << 5, nt = (tile % tilesN) << 5;
    #pragma unroll
    for (int r = 0; r < 4; r++)
        t[ty + 8*r][tx] = s[(size_t)(kt + ty + 8*r) * N + nt + tx];
    __syncthreads();
    #pragma unroll
    for (int r = 0; r < 4; r++)
        d[(size_t)(nt + ty + 8*r) * K + kt + tx] = __float2half(t[tx][ty + 8*r]);
}

// ---------------- cp.async helpers -----------------------------------------
__device__ __forceinline__ void cp16(void* smem, const void* g) {
    uint32_t s = (uint32_t)__cvta_generic_to_shared(smem);
    asm volatile("cp.async.cg.shared.global [%0], [%1], 16;\n" :: "r"(s), "l"(g));
}
#define CP_COMMIT() asm volatile("cp.async.commit_group;\n" ::: "memory")
#define CP_WAIT2()  asm volatile("cp.async.wait_group 2;\n" ::: "memory")
#define CP_WAIT0()  asm volatile("cp.async.wait_group 0;\n" ::: "memory")

// ---------------- fp16 HMMA GEMM --------------------------------------------
__device__ __forceinline__ void mma16816(float* c, const uint32_t* a,
                                         uint32_t b0, uint32_t b1) {
    asm("mma.sync.aligned.m16n8k16.row.col.f32.f16.f16.f32 "
        "{%0,%1,%2,%3},{%4,%5,%6,%7},{%8,%9},{%0,%1,%2,%3};"
        : "+f"(c[0]), "+f"(c[1]), "+f"(c[2]), "+f"(c[3])
        : "r"(a[0]), "r"(a[1]), "r"(a[2]), "r"(a[3]), "r"(b0), "r"(b1));
}

template<int ACT, bool WF, bool WH>
__global__ void hgemm(const __half* __restrict__ A, const __half* __restrict__ Bt,
                      const float* __restrict__ bias, float* __restrict__ C,
                      __half* __restrict__ Ch, int M, int N, int K) {
    __shared__ __align__(16) __half As[4][64][24];
    __shared__ __align__(16) __half Bs[4][64][24];
    const int tid = threadIdx.x, lane = tid & 31, wid = tid >> 5;
    const int wmi = wid >> 1, wni = wid & 1;
    const int brow = blockIdx.y * 64, bcol = blockIdx.x * 64;
    const int g = lane >> 2, t4 = lane & 3;
    const int arow = tid >> 1, aseg = (tid & 1) * 8;

    const __half* aGp = A + (size_t)(brow + arow) * K + aseg;
    const __half* bGp = Bt + (size_t)(bcol + arow) * K + aseg;

    const int T = K >> 4;
    #pragma unroll
    for (int pt = 0; pt < 3; pt++) {
        if (pt < T) {
            cp16(&As[pt][arow][aseg], aGp + (pt << 4));
            cp16(&Bs[pt][arow][aseg], bGp + (pt << 4));
        }
        CP_COMMIT();
    }

    float acc[2][4][4] = {};
    for (int t = 0; t < T; t++) {
        CP_WAIT2();
        __syncthreads();
        if (t + 3 < T) {
            int sn = (t + 3) & 3, k0 = (t + 3) << 4;
            cp16(&As[sn][arow][aseg], aGp + k0);
            cp16(&Bs[sn][arow][aseg], bGp + k0);
        }
        CP_COMMIT();
        const int s = t & 3;
        uint32_t a[2][4], b[4][2];
        #pragma unroll
        for (int mi = 0; mi < 2; mi++) {
            int r0 = wmi * 32 + mi * 16 + g;
            a[mi][0] = *(const uint32_t*)&As[s][r0][2*t4];
            a[mi][1] = *(const uint32_t*)&As[s][r0 + 8][2*t4];
            a[mi][2] = *(const uint32_t*)&As[s][r0][2*t4 + 8];
            a[mi][3] = *(const uint32_t*)&As[s][r0 + 8][2*t4 + 8];
        }
        #pragma unroll
        for (int ni = 0; ni < 4; ni++) {
            int n0 = wni * 32 + ni * 8 + g;
            b[ni][0] = *(const uint32_t*)&Bs[s][n0][2*t4];
            b[ni][1] = *(const uint32_t*)&Bs[s][n0][2*t4 + 8];
        }
        #pragma unroll
        for (int mi = 0; mi < 2; mi++)
            #pragma unroll
            for (int ni = 0; ni < 4; ni++)
                mma16816(acc[mi][ni], a[mi], b[ni][0], b[ni][1]);
        __syncthreads();
    }
    #pragma unroll
    for (int mi = 0; mi < 2; mi++) {
        #pragma unroll
        for (int ni = 0; ni < 4; ni++) {
            int r = brow + wmi * 32 + mi * 16 + g;
            int c = bcol + wni * 32 + ni * 8 + t4 * 2;
            #pragma unroll
            for (int e = 0; e < 4; e++) {
                int rr = r + ((e >= 2) ? 8 : 0);
                int cc = c + (e & 1);
                float v = acc[mi][ni][e];
                if (bias) v += bias[cc];
                if (ACT == 1) v = tanhf(v);
                if (ACT == 2) v = fmaxf(v, 0.0f);
                if (WF) C[(size_t)rr * N + cc] = v;
                if (WH) Ch[(size_t)rr * N + cc] = __float2half(v);
            }
        }
    }
}

// ---------------- batched QK^T GEMM: S[bh] = Qn @ Kn^T -----------------------
__global__ void __launch_bounds__(128)
qk_gemm(const __half* __restrict__ H2h, float* __restrict__ S) {
    __shared__ __align__(16) __half As[2][64][24];
    __shared__ __align__(16) __half Bs[2][64][24];
    const int z = blockIdx.z, b = z >> 3, h = z & 7;
    const int tid = threadIdx.x, lane = tid & 31, wid = tid >> 5;
    const int wmi = wid >> 1, wni = wid & 1;
    const int brow = blockIdx.y * 64, bcol = blockIdx.x * 64;
    const int g = lane >> 2, t4 = lane & 3;
    const int arow = tid >> 1, aseg = (tid & 1) * 8;

    const __half* Ab = H2h + (size_t)(b*NN)*HT + h*TOT;      // Qn base
    const __half* aGp = Ab + (size_t)(brow + arow) * HT + aseg;
    const __half* bGp = Ab + KS + (size_t)(bcol + arow) * HT + aseg;  // Kn
    cp16(&As[0][arow][aseg], aGp);
    cp16(&Bs[0][arow][aseg], bGp);
    cp16(&As[1][arow][aseg], aGp + 16);
    cp16(&Bs[1][arow][aseg], bGp + 16);
    CP_COMMIT();
    CP_WAIT0();
    __syncthreads();

    float acc[2][4][4] = {};
    #pragma unroll
    for (int s = 0; s < 2; s++) {
        uint32_t a[2][4], b2[4][2];
        #pragma unroll
        for (int mi = 0; mi < 2; mi++) {
            int r0 = wmi * 32 + mi * 16 + g;
            a[mi][0] = *(const uint32_t*)&As[s][r0][2*t4];
            a[mi][1] = *(const uint32_t*)&As[s][r0 + 8][2*t4];
            a[mi][2] = *(const uint32_t*)&As[s][r0][2*t4 + 8];
            a[mi][3] = *(const uint32_t*)&As[s][r0 + 8][2*t4 + 8];
        }
        #pragma unroll
        for (int ni = 0; ni < 4; ni++) {
            int n0 = wni * 32 + ni * 8 + g;
            b2[ni][0] = *(const uint32_t*)&Bs[s][n0][2*t4];
            b2[ni][1] = *(const uint32_t*)&Bs[s][n0][2*t4 + 8];
        }
        #pragma unroll
        for (int mi = 0; mi < 2; mi++)
            #pragma unroll
            for (int ni = 0; ni < 4; ni++)
                mma16816(acc[mi][ni], a[mi], b2[ni][0], b2[ni][1]);
    }
    float* Sp = S + (size_t)z * NN * NN;
    #pragma unroll
    for (int mi = 0; mi < 2; mi++)
        #pragma unroll
        for (int ni = 0; ni < 4; ni++) {
            int r = brow + wmi * 32 + mi * 16 + g;
            int c = bcol + wni * 32 + ni * 8 + t4 * 2;
            #pragma unroll
            for (int e = 0; e < 4; e++) {
                int rr = r + ((e >= 2) ? 8 : 0);
                int cc = c + (e & 1);
                Sp[(size_t)rr * NN + cc] = acc[mi][ni][e];
            }
        }
}

// ---------------- Vt extraction: Vt[bh][v][j] = H2h[b*192+j][h*112+64+v] ----
__global__ void vt_kernel(const __half* __restrict__ H2h, __half* __restrict__ Vt) {
    int z = blockIdx.x, b = z >> 3, h = z & 7;
    int j = threadIdx.x;   // 192
    const uint4* src = (const uint4*)(H2h + (size_t)(b*NN + j)*HT + h*TOT + 2*KS);
    __half v[32];
    #pragma unroll
    for (int q = 0; q < 4; q++) ((uint4*)v)[q] = src[q];
    __half* dst = Vt + (size_t)z * VS * NN + j;
    #pragma unroll
    for (int vv = 0; vv < VS; vv++) dst[(size_t)vv * NN] = v[vv];
}

// ---------------- attn_rows: softmax + route (all heads share R) ------------
// grid (BB, 48); 256 threads = 8 warps = 8 heads; 4 rows per CTA.
#define WDS 130
__global__ void __launch_bounds__(256)
attn_rows(const __half* __restrict__ H2h, const float* __restrict__ S,
          const float* __restrict__ R, const float* __restrict__ Wd_l,
          const float* __restrict__ Wr_l, const float* __restrict__ amask,
          __half* __restrict__ P, float* __restrict__ ctxr) {
    extern __shared__ float sm[];
    float* sR    = sm;               // [16][192]
    float* sWr   = sR + RS*NN;       // [16][256]
    float* sWd   = sWr + RS*HID;     // [16][130]
    float* sMask = sWd + RS*WDS;     // 192
    float* sScr  = sMask + NN;       // [8][32][17]
    float* sPRf  = sScr + 8*32*17;   // [8][16]

    const int tid = threadIdx.x, lane = tid & 31, h = tid >> 5;
    const int b = blockIdx.x;

    for (int i2 = tid; i2 < RS*HID; i2 += 256) sWr[i2] = Wr_l[i2];
    for (int i2 = tid; i2 < RS*128; i2 += 256)
        sWd[(i2 >> 7) * WDS + (i2 & 127)] = Wd_l[i2];
    if (tid < NN) sMask[tid] = (1.0f - amask[b*NN + tid]) * -10000.0f;
    __syncthreads();

    float* scr = sScr + h*32*17;
    float* prf = sPRf + h*16;

    for (int r = 0; r < 4; r++) {
        const int i = blockIdx.y * 4 + r;
        const size_t row = (size_t)(b*NN + i);
        // cooperative R load (coalesced from transposed layout)
        const float* Rg = R + row * RS * NN;
        #pragma unroll
        for (int q = 0; q < 12; q++) sR[tid + q*256] = Rg[tid + q*256];
        __syncthreads();

        // A[h][s] from Qr (fp16) x Wd
        const __half* qrp = H2h + row*HT + h*TOT + 2*KS + VS;
        float myA = 0.0f;
        if (lane < RS) {
            #pragma unroll
            for (int k = 0; k < KRS; k++)
                myA = fmaf(__half2float(qrp[k]), sWd[lane*WDS + h*KRS + k], myA);
        }
        float av[16];
        #pragma unroll
        for (int s = 0; s < 16; s++) av[s] = __shfl_sync(0xffffffffu, myA, s);

        // fused scores+exp+PR
        const float* Sp = S + ((size_t)(b*HEADS + h)*NN + i)*NN;
        float pr[16] = {}, ej[6];
        float esum = 0.0f;
        #pragma unroll
        for (int jj = 0; jj < 6; jj++) {
            const int j = jj*32 + lane;
            float rv[16];
            #pragma unroll
            for (int s = 0; s < 16; s++) rv[s] = sR[s*NN + j];
            float sc = Sp[j];
            #pragma unroll
            for (int s = 0; s < 16; s++) sc = fmaf(av[s], rv[s], sc);
            float e = __expf(sc * SCALE + sMask[j]);
            esum += e; ej[jj] = e;
            #pragma unroll
            for (int s = 0; s < 16; s++) pr[s] = fmaf(e, rv[s], pr[s]);
        }
        float a = esum;
        #pragma unroll
        for (int o = 16; o; o >>= 1) a += __shfl_xor_sync(0xffffffffu, a, o);
        float inv = 1.0f / a;

        // write P (fp16, normalized)
        __half* Pp = P + ((size_t)(b*HEADS + h)*NN + i)*NN;
        #pragma unroll
        for (int jj = 0; jj < 6; jj++)
            Pp[jj*32 + lane] = __float2half(ej[jj] * inv);

        // PR cross-lane reduce
        float* my = scr + lane*17;
        #pragma unroll
        for (int s = 0; s < 16; s++) my[s] = pr[s];
        __syncwarp();
        if (lane < 16) {
            float a2 = 0.0f;
            const float* col = scr + lane;
            #pragma unroll
            for (int l = 0; l < 32; l++) a2 += col[l*17];
            prf[lane] = a2 * inv;
        }
        __syncwarp();

        // route context: ctxr[row][h*32+v]
        float c = 0.0f;
        #pragma unroll
        for (int s = 0; s < 16; s++)
            c = fmaf(prf[s], sWr[s*HID + h*VS + lane], c);
        ctxr[row*HID + h*VS + lane] = c;
        __syncthreads();   // protect sR before next row
    }
}

// ---------------- batched PV GEMM: ctx[bh] = P @ Vt^T + ctxr -----------------
__global__ void __launch_bounds__(128)
pv_gemm(const __half* __restrict__ P, const __half* __restrict__ Vt,
        const float* __restrict__ ctxr, __half* __restrict__ ctxh) {
    __shared__ __align__(16) __half As[4][64][24];
    __shared__ __align__(16) __half Bs[4][32][24];
    const int z = blockIdx.z, b = z >> 3, h = z & 7;
    const int tid = threadIdx.x, lane = tid & 31, wmi = tid >> 5;
    const int brow = blockIdx.y * 64;
    const int g = lane >> 2, t4 = lane & 3;
    const int arow = tid >> 1, aseg = (tid & 1) * 8;

    const __half* aGp = P + (size_t)z*NN*NN + (size_t)(brow + arow)*NN + aseg;
    const __half* bGp = Vt + (size_t)z*VS*NN + (size_t)arow*NN + aseg;   // tid<64

    const int T = NN >> 4;   // 12
    #pragma unroll
    for (int pt = 0; pt < 3; pt++) {
        cp16(&As[pt][arow][aseg], aGp + (pt << 4));
        if (tid < 64) cp16(&Bs[pt][arow][aseg], bGp + (pt << 4));
        CP_COMMIT();
    }

    float acc[4][4] = {};
    for (int t = 0; t < T; t++) {
        CP_WAIT2();
        __syncthreads();
        if (t + 3 < T) {
            int sn = (t + 3) & 3, k0 = (t + 3) << 4;
            cp16(&As[sn][arow][aseg], aGp + k0);
            if (tid < 64) cp16(&Bs[sn][arow][aseg], bGp + k0);
        }
        CP_COMMIT();
        const int s = t & 3;
        uint32_t a[4], b2[4][2];
        int r0 = wmi * 16 + g;
        a[0] = *(const uint32_t*)&As[s][r0][2*t4];
        a[1] = *(const uint32_t*)&As[s][r0 + 8][2*t4];
        a[2] = *(const uint32_t*)&As[s][r0][2*t4 + 8];
        a[3] = *(const uint32_t*)&As[s][r0 + 8][2*t4 + 8];
        #pragma unroll
        for (int ni = 0; ni < 4; ni++) {
            int n0 = ni * 8 + g;
            b2[ni][0] = *(const uint32_t*)&Bs[s][n0][2*t4];
            b2[ni][1] = *(const uint32_t*)&Bs[s][n0][2*t4 + 8];
        }
        #pragma unroll
        for (int ni = 0; ni < 4; ni++)
            mma16816(acc[ni], a, b2[ni][0], b2[ni][1]);
        __syncthreads();
    }
    #pragma unroll
    for (int ni = 0; ni < 4; ni++) {
        int r = brow + wmi * 16 + g;
        int c = ni * 8 + t4 * 2;
        #pragma unroll
        for (int e = 0; e < 4; e++) {
            int rr = r + ((e >= 2) ? 8 : 0);
            int cc = c + (e & 1);
            size_t idx = (size_t)(b*NN + rr) * HID + h*VS + cc;
            ctxh[idx] = __float2half(acc[ni][e] + ctxr[idx]);
        }
    }
}

// ---------------- warp-per-row LayerNorm ------------------------------------
__device__ __forceinline__ float warpsum(float a) {
    #pragma unroll
    for (int o = 16; o; o >>= 1) a += __shfl_xor_sync(0xffffffffu, a, o);
    return a;
}

__device__ __forceinline__ void ln_core(const float* v, const float* g,
                                        const float* bt, float* out,
                                        __half* outh, int row, int lane) {
    float s = 0.0f;
    #pragma unroll
    for (int q = 0; q < 8; q++) s += v[q];
    float mean = warpsum(s) * (1.0f / HID);
    float s2 = 0.0f;
    #pragma unroll
    for (int q = 0; q < 8; q++) { float d = v[q] - mean; s2 += d * d; }
    float inv = rsqrtf(warpsum(s2) * (1.0f / HID) + LN_EPS);
    float4 g0 = ((const float4*)g)[lane],  g1 = ((const float4*)g)[lane + 32];
    float4 t0 = ((const float4*)bt)[lane], t1 = ((const float4*)bt)[lane + 32];
    float o[8];
    o[0] = g0.x * (v[0]-mean)*inv + t0.x; o[1] = g0.y * (v[1]-mean)*inv + t0.y;
    o[2] = g0.z * (v[2]-mean)*inv + t0.z; o[3] = g0.w * (v[3]-mean)*inv + t0.w;
    o[4] = g1.x * (v[4]-mean)*inv + t1.x; o[5] = g1.y * (v[5]-mean)*inv + t1.y;
    o[6] = g1.z * (v[6]-mean)*inv + t1.z; o[7] = g1.w * (v[7]-mean)*inv + t1.w;
    float4* op = (float4*)(out + (size_t)row * HID);
    op[lane]      = make_float4(o[0], o[1], o[2], o[3]);
    op[lane + 32] = make_float4(o[4], o[5], o[6], o[7]);
    __half2* hp = (__half2*)(outh + (size_t)row * HID);
    hp[lane*2]        = __floats2half2_rn(o[0], o[1]);
    hp[lane*2 + 1]    = __floats2half2_rn(o[2], o[3]);
    hp[64 + lane*2]   = __floats2half2_rn(o[4], o[5]);
    hp[64 + lane*2+1] = __floats2half2_rn(o[6], o[7]);
}

__global__ void ln_res_kernel(const float* __restrict__ x, const float* __restrict__ res,
                              const float* __restrict__ g, const float* __restrict__ bt,
                              float* __restrict__ out, __half* __restrict__ outh) {
    int warp = threadIdx.x >> 5, lane = threadIdx.x & 31;
    int row = blockIdx.x * 8 + warp;
    const float4* xp = (const float4*)(x + (size_t)row * HID);
    const float4* rp = (const float4*)(res + (size_t)row * HID);
    float4 a0 = xp[lane], a1 = xp[lane + 32];
    float4 b0 = rp[lane], b1 = rp[lane + 32];
    float v[8] = {a0.x + b0.x, a0.y + b0.y, a0.z + b0.z, a0.w + b0.w,
                  a1.x + b1.x, a1.y + b1.y, a1.z + b1.z, a1.w + b1.w};
    ln_core(v, g, bt, out, outh, row, lane);
}

__global__ void embed_ln_kernel(const float* __restrict__ pre, const int* __restrict__ ids,
                                const float* __restrict__ emb, const float* __restrict__ g,
                                const float* __restrict__ bt, float* __restrict__ out,
                                __half* __restrict__ outh) {
    int warp = threadIdx.x >> 5, lane = threadIdx.x & 31;
    int row = blockIdx.x * 8 + warp;
    int id = ids[row];
    const float4* xp = (const float4*)(pre + (size_t)row * HID);
    const float4* ep = (const float4*)(emb + (size_t)id * HID);
    float4 a0 = xp[lane], a1 = xp[lane + 32];
    float4 b0 = ep[lane], b1 = ep[lane + 32];
    float v[8] = {a0.x + b0.x, a0.y + b0.y, a0.z + b0.z, a0.w + b0.w,
                  a1.x + b1.x, a1.y + b1.y, a1.z + b1.z, a1.w + b1.w};
    ln_core(v, g, bt, out, outh, row, lane);
}

// ---------------- route embedding -> TRANSPOSED R [bi][s][j] ---------------
__global__ void route_kernel(const float* __restrict__ rd,
                             const float* __restrict__ rw1, const float* __restrict__ rb1,
                             const float* __restrict__ rw2, const float* __restrict__ rb2,
                             const float* __restrict__ gg, const float* __restrict__ bb,
                             float* __restrict__ R) {
    __shared__ float s_rw1[RF*RS], s_rw2[RS*RS], s_rb1[RS], s_rb2[RS], s_g[RS], s_b[RS];
    int tid = threadIdx.x;
    for (int i = tid; i < RF*RS; i += blockDim.x) s_rw1[i] = rw1[i];
    for (int i = tid; i < RS*RS; i += blockDim.x) s_rw2[i] = rw2[i];
    if (tid < RS) { s_rb1[tid]=rb1[tid]; s_rb2[tid]=rb2[tid]; s_g[tid]=gg[tid]; s_b[tid]=bb[tid]; }
    __syncthreads();
    size_t idx = (size_t)blockIdx.x * blockDim.x + tid;
    const float4* rp = (const float4*)(rd + idx * RF);
    float4 v0 = rp[0], v1 = rp[1];
    float x[RF] = {v0.x, v0.y, v0.z, v0.w, v1.x, v1.y, v1.z, v1.w};
    float h[RS];
    #pragma unroll
    for (int s = 0; s < RS; s++) {
        float a = s_rb1[s];
        #pragma unroll
        for (int f = 0; f < RF; f++) a += x[f] * s_rw1[f*RS + s];
        h[s] = tanhf(a);
    }
    float r[RS]; float mean = 0.0f;
    #pragma unroll
    for (int t = 0; t < RS; t++) {
        float a = s_rb2[t];
        #pragma unroll
        for (int s = 0; s < RS; s++) a += h[s] * s_rw2[s*RS + t];
        r[t] = a; mean += a;
    }
    mean *= (1.0f / RS);
    float var = 0.0f;
    #pragma unroll
    for (int t = 0; t < RS; t++) { float d = r[t] - mean; var += d * d; }
    var *= (1.0f / RS);
    float inv = rsqrtf(var + LN_EPS);
    size_t bi = idx / NN;
    int j = (int)(idx % NN);
    float* dst = R + (bi * RS) * NN + j;
    #pragma unroll
    for (int t = 0; t < RS; t++)
        dst[(size_t)t * NN] = s_g[t] * (r[t] - mean) * inv + s_b[t];
}

// ---------------- host launch ------------------------------------------------
extern "C" void kernel_launch(void* const* d_in, const int* in_sizes, int n_in,
                              void* d_out, int out_size) {
    const int*   node_ids      = (const int*)  d_in[0];
    const float* node_features = (const float*)d_in[1];
    const float* route_data    = (const float*)d_in[2];
    const float* amask         = (const float*)d_in[3];
    const float* emb           = (const float*)d_in[4];
    const float* fw1 = (const float*)d_in[5];  const float* fb1 = (const float*)d_in[6];
    const float* fw2 = (const float*)d_in[7];  const float* fb2 = (const float*)d_in[8];
    const float* eg  = (const float*)d_in[9];  const float* ebt = (const float*)d_in[10];
    const float* rw1 = (const float*)d_in[11]; const float* rb1 = (const float*)d_in[12];
    const float* rw2 = (const float*)d_in[13]; const float* rb2 = (const float*)d_in[14];
    const float* rg  = (const float*)d_in[15]; const float* rbt = (const float*)d_in[16];
    const float* W      = (const float*)d_in[17];
    const float* Wd     = (const float*)d_in[18];
    const float* Wroute = (const float*)d_in[19];
    const float* Wo     = (const float*)d_in[20];
    const float* bo     = (const float*)d_in[21];
    const float* og     = (const float*)d_in[22]; const float* obt = (const float*)d_in[23];
    const float* Wi     = (const float*)d_in[24]; const float* bi  = (const float*)d_in[25];
    const float* Wo2    = (const float*)d_in[26]; const float* bo2 = (const float*)d_in[27];
    const float* fg     = (const float*)d_in[28]; const float* fbt = (const float*)d_in[29];
    float* out = (float*)d_out;

    float *pH, *pR, *pS, *pCtxr, *pAttn, *pTmp;
    cudaGetSymbolAddress((void**)&pH,    g_H);
    cudaGetSymbolAddress((void**)&pR,    g_R);
    cudaGetSymbolAddress((void**)&pS,    g_S);
    cudaGetSymbolAddress((void**)&pCtxr, g_ctxr);
    cudaGetSymbolAddress((void**)&pAttn, g_attn);
    cudaGetSymbolAddress((void**)&pTmp,  g_tmp);

    __half *pNfh, *pFeat1h, *pHh, *pH2h, *pP, *pVth, *pCtxh, *pAttnh, *pInterh;
    __half *pFw1t, *pFw2t, *pWt, *pWot, *pWit, *pWo2t;
    cudaGetSymbolAddress((void**)&pNfh,    g_nfh);
    cudaGetSymbolAddress((void**)&pFeat1h, g_feat1h);
    cudaGetSymbolAddress((void**)&pHh,     g_Hh);
    cudaGetSymbolAddress((void**)&pH2h,    g_H2h);
    cudaGetSymbolAddress((void**)&pP,      g_P);
    cudaGetSymbolAddress((void**)&pVth,    g_Vth);
    cudaGetSymbolAddress((void**)&pCtxh,   g_ctxh);
    cudaGetSymbolAddress((void**)&pAttnh,  g_attnh);
    cudaGetSymbolAddress((void**)&pInterh, g_interh);
    cudaGetSymbolAddress((void**)&pFw1t,   g_fw1t);
    cudaGetSymbolAddress((void**)&pFw2t,   g_fw2t);
    cudaGetSymbolAddress((void**)&pWt,     g_Wt);
    cudaGetSymbolAddress((void**)&pWot,    g_Wot);
    cudaGetSymbolAddress((void**)&pWit,    g_Wit);
    cudaGetSymbolAddress((void**)&pWo2t,   g_Wo2t);

    const int AR_SMEM = (RS*NN + RS*HID + RS*WDS + NN + 8*32*17 + 8*16)
                        * (int)sizeof(float);
    cudaFuncSetAttribute(attn_rows, cudaFuncAttributeMaxDynamicSharedMemorySize, AR_SMEM);

    // --- 0: weight conversion / transposition ---
    CvtJobs J;
    int ji = 0;
    J.src[ji]=node_features; J.dst[ji]=pNfh;  J.K[ji]=ROWS; J.N[ji]=NF;  J.tiles[ji]=(ROWS*NF+1023)/1024; J.plain[ji]=1; ji++;
    J.src[ji]=fw1;           J.dst[ji]=pFw1t; J.K[ji]=NF;   J.N[ji]=HID; J.tiles[ji]=(NF/32)*(HID/32);    J.plain[ji]=0; ji++;
    J.src[ji]=fw2;           J.dst[ji]=pFw2t; J.K[ji]=HID;  J.N[ji]=HID; J.tiles[ji]=(HID/32)*(HID/32);   J.plain[ji]=0; ji++;
    for (int l = 0; l < LAYERS; l++) {
        J.src[ji]=W + (size_t)l*HID*HT; J.dst[ji]=pWt + (size_t)l*HT*HID;
        J.K[ji]=HID; J.N[ji]=HT; J.tiles[ji]=(HID/32)*(HT/32); J.plain[ji]=0; ji++;
    }
    for (int l = 0; l < LAYERS; l++) {
        J.src[ji]=Wo + (size_t)l*HID*HID; J.dst[ji]=pWot + (size_t)l*HID*HID;
        J.K[ji]=HID; J.N[ji]=HID; J.tiles[ji]=(HID/32)*(HID/32); J.plain[ji]=0; ji++;
    }
    for (int l = 0; l < LAYERS; l++) {
        J.src[ji]=Wi + (size_t)l*HID*IM; J.dst[ji]=pWit + (size_t)l*IM*HID;
        J.K[ji]=HID; J.N[ji]=IM; J.tiles[ji]=(HID/32)*(IM/32); J.plain[ji]=0; ji++;
    }
    for (int l = 0; l < LAYERS; l++) {
        J.src[ji]=Wo2 + (size_t)l*IM*HID; J.dst[ji]=pWo2t + (size_t)l*HID*IM;
        J.K[ji]=IM; J.N[ji]=HID; J.tiles[ji]=(IM/32)*(HID/32); J.plain[ji]=0; ji++;
    }
    int maxTiles = 0;
    for (int q = 0; q < NJOBS; q++) if (J.tiles[q] > maxTiles) maxTiles = J.tiles[q];
    cvt_kernel<<<dim3(maxTiles, NJOBS), dim3(32, 8)>>>(J);

    // --- embedding feature MLP ---
    hgemm<1,false,true><<<dim3(HID/64, ROWS/64), 128>>>(
        pNfh, pFw1t, fb1, nullptr, pFeat1h, ROWS, HID, NF);
    hgemm<0,true,false><<<dim3(HID/64, ROWS/64), 128>>>(
        pFeat1h, pFw2t, fb2, pTmp, nullptr, ROWS, HID, HID);

    // --- embeddings LN ---
    embed_ln_kernel<<<ROWS/8, 256>>>(pTmp, node_ids, emb, eg, ebt, pH, pHh);

    // --- route embeddings (transposed output) ---
    route_kernel<<<NPAIR/256, 256>>>(route_data, rw1, rb1, rw2, rb2, rg, rbt, pR);

    // --- layers ---
    for (int l = 0; l < LAYERS; l++) {
        const __half* Wt_l   = pWt   + (size_t)l * HT * HID;
        const __half* Wot_l  = pWot  + (size_t)l * HID * HID;
        const __half* Wit_l  = pWit  + (size_t)l * IM * HID;
        const __half* Wo2t_l = pWo2t + (size_t)l * HID * IM;
        const float* Wd_l  = Wd     + (size_t)l * RS * (HEADS*KRS);
        const float* Wr_l  = Wroute + (size_t)l * RS * (HEADS*VS);
        const float* bo_l  = bo     + (size_t)l * HID;
        const float* og_l  = og     + (size_t)l * HID;
        const float* ob_l  = obt    + (size_t)l * HID;
        const float* bi_l  = bi     + (size_t)l * IM;
        const float* b2_l  = bo2    + (size_t)l * HID;
        const float* fg_l  = fg     + (size_t)l * HID;
        const float* fb_l  = fbt    + (size_t)l * HID;

        // QKV projection -> fp16 H2h
        hgemm<0,false,true><<<dim3(HT/64, ROWS/64), 128>>>(
            pHh, Wt_l, nullptr, nullptr, pH2h, ROWS, HT, HID);
        // V transpose extraction
        vt_kernel<<<NBH, NN>>>(pH2h, pVth);
        // batched QK^T -> S (fp32)
        qk_gemm<<<dim3(NN/64, NN/64, NBH), 128>>>(pH2h, pS);
        // softmax + route (R shared across heads) -> P, ctxr
        attn_rows<<<dim3(BB, NN/4), 256, AR_SMEM>>>(pH2h, pS, pR, Wd_l, Wr_l,
                                                    amask, pP, pCtxr);
        // batched P@V + ctxr -> ctxh (fp16)
        pv_gemm<<<dim3(1, NN/64, NBH), 128>>>(pP, pVth, pCtxr, pCtxh);
        // output projection + residual LN
        hgemm<0,true,false><<<dim3(HID/64, ROWS/64), 128>>>(
            pCtxh, Wot_l, bo_l, pTmp, nullptr, ROWS, HID, HID);
        ln_res_kernel<<<ROWS/8, 256>>>(pTmp, pH, og_l, ob_l, pAttn, pAttnh);
        // FFN
        hgemm<2,false,true><<<dim3(IM/64, ROWS/64), 128>>>(
            pAttnh, Wit_l, bi_l, nullptr, pInterh, ROWS, IM, HID);
        hgemm<0,true,false><<<dim3(HID/64, ROWS/64), 128>>>(
            pInterh, Wo2t_l, b2_l, pTmp, nullptr, ROWS, HID, IM);
        float* dst = (l == LAYERS - 1) ? out : pH;
        ln_res_kernel<<<ROWS/8, 256>>>(pTmp, pAttn, fg_l, fb_l, dst, pHh);
    }
    (void)in_sizes; (void)n_in; (void)out_size;
}